// round 11
// baseline (speedup 1.0000x reference)
#include <cuda_runtime.h>
#include <cuda_bf16.h>
#include <cuda_fp16.h>
#include <math.h>
#include <stdint.h>

#define B_  16
#define T_  128
#define E_  300
#define H_  1024
#define V_  32000
#define BT_ (B_*T_)

// ---- output section offsets (flattened tuple) ----
#define OFF_STYLE   65536000LL
#define OFF_CONTENT 65537024LL
#define OFF_MU_S    65540096LL
#define OFF_LV_S    65541120LL
#define OFF_MU_C    65542144LL
#define OFF_LV_C    65545216LL

// ---- scratch (device globals; no allocation allowed) ----
__device__ float g_e[BT_*E_];
__device__ float g_sos[E_];
__device__ float g_din[BT_*E_];
__device__ float g_xg_enc[BT_*3*H_];
__device__ float g_xg_dec[BT_*3*H_];
__device__ float g_hA[B_*H_];
__device__ float g_hB[B_*H_];
__device__ float g_zin[B_*256];

// fp16 buffers for tensor-core logits GEMM
__device__ __align__(256) __half g_ys16h[BT_*H_];
__device__ __align__(256) __half g_ys16l[BT_*H_];
__device__ __align__(256) __half g_W16[(size_t)V_*H_];

// distributed barrier: one monotone generation word per block
__device__ __align__(128) unsigned g_flags[128];

// ============================================================
// small PTX helpers
// ============================================================
typedef unsigned long long u64;

__device__ __forceinline__ u64 fma2(u64 a, u64 b, u64 c) {
    u64 d; asm("fma.rn.f32x2 %0, %1, %2, %3;" : "=l"(d) : "l"(a), "l"(b), "l"(c));
    return d;
}
__device__ __forceinline__ float2 upk(u64 v) {
    float2 r; asm("mov.b64 {%0,%1}, %2;" : "=f"(r.x), "=f"(r.y) : "l"(v));
    return r;
}
__device__ __forceinline__ void cpa16(unsigned dst, const void* src) {
    asm volatile("cp.async.cg.shared.global [%0], [%1], 16;\n" :: "r"(dst), "l"(src));
}
__device__ __forceinline__ void cp_commit() {
    asm volatile("cp.async.commit_group;\n");
}
__device__ __forceinline__ void ldsm_x4(uint32_t* r, unsigned addr) {
    asm volatile("ldmatrix.sync.aligned.m8n8.x4.shared.b16 {%0,%1,%2,%3}, [%4];\n"
        : "=r"(r[0]), "=r"(r[1]), "=r"(r[2]), "=r"(r[3]) : "r"(addr));
}
__device__ __forceinline__ void ldsm_x2(uint32_t* r, unsigned addr) {
    asm volatile("ldmatrix.sync.aligned.m8n8.x2.shared.b16 {%0,%1}, [%2];\n"
        : "=r"(r[0]), "=r"(r[1]) : "r"(addr));
}
__device__ __forceinline__ void mma16816h(float* d, const uint32_t* a, const uint32_t* b) {
    asm volatile("mma.sync.aligned.m16n8k16.row.col.f32.f16.f16.f32 "
        "{%0,%1,%2,%3}, {%4,%5,%6,%7}, {%8,%9}, {%0,%1,%2,%3};\n"
        : "+f"(d[0]), "+f"(d[1]), "+f"(d[2]), "+f"(d[3])
        : "r"(a[0]), "r"(a[1]), "r"(a[2]), "r"(a[3]), "r"(b[0]), "r"(b[1]));
}

// ============================================================
// Embedding gather + LayerNorm.  blocks 0..2047: tokens, block 2048: sos
// ============================================================
__global__ void embed_ln_kernel(const int* __restrict__ x, const int* __restrict__ sos,
                                const float* __restrict__ emb,
                                const float* __restrict__ lg, const float* __restrict__ lb,
                                float* __restrict__ e_out, float* __restrict__ sos_out)
{
    __shared__ float sv[E_];
    __shared__ float rbuf[4];
    int bt = blockIdx.x;
    int tok; float* dst;
    if (bt < BT_) { tok = x[bt]; dst = e_out + (long)bt*E_; }
    else          { tok = sos[0]; dst = sos_out; }
    const float* row = emb + (long)tok * E_;
    int tid = threadIdx.x;

    float s = 0.f;
    for (int i = tid; i < E_; i += 128) { float v = row[i]; sv[i] = v; s += v; }
    #pragma unroll
    for (int o = 16; o; o >>= 1) s += __shfl_xor_sync(0xffffffffu, s, o);
    if ((tid & 31) == 0) rbuf[tid >> 5] = s;
    __syncthreads();
    float mu = (rbuf[0]+rbuf[1]+rbuf[2]+rbuf[3]) * (1.f/(float)E_);

    float s2 = 0.f;
    for (int i = tid; i < E_; i += 128) { float d = sv[i]-mu; s2 += d*d; }
    #pragma unroll
    for (int o = 16; o; o >>= 1) s2 += __shfl_xor_sync(0xffffffffu, s2, o);
    __syncthreads();
    if ((tid & 31) == 0) rbuf[tid >> 5] = s2;
    __syncthreads();
    float var  = (rbuf[0]+rbuf[1]+rbuf[2]+rbuf[3]) * (1.f/(float)E_);
    float rstd = rsqrtf(var + 1e-5f);

    for (int i = tid; i < E_; i += 128)
        dst[i] = (sv[i]-mu)*rstd*lg[i] + lb[i];
}

// ============================================================
// dec_in assembly: dec_in[b,0]=sos_e ; dec_in[b,t]=e[b,t-1]
// ============================================================
__global__ void make_din_kernel(const float* __restrict__ e, const float* __restrict__ sos,
                                float* __restrict__ din)
{
    int i = blockIdx.x*blockDim.x + threadIdx.x;
    if (i >= BT_*E_) return;
    int bt = i / E_, c = i % E_;
    int t = bt & (T_-1);
    din[i] = (t == 0) ? sos[c] : e[(long)(bt-1)*E_ + c];
}

// ============================================================
// Batched SGEMM (fp32) for the two xg input-gate GEMMs.
// ============================================================
__global__ void __launch_bounds__(256, 1) sgemm_nt_bias2(
    const float* __restrict__ A0, const float* __restrict__ B0,
    const float* __restrict__ b0v, float* __restrict__ C0,
    const float* __restrict__ A1, const float* __restrict__ B1,
    const float* __restrict__ b1v, float* __restrict__ C1,
    int M, int N, int K)
{
    const float* A    = blockIdx.z ? A1 : A0;
    const float* Bm   = blockIdx.z ? B1 : B0;
    const float* bias = blockIdx.z ? b1v : b0v;
    float*       C    = blockIdx.z ? C1 : C0;

    __shared__ float As[8][128];
    __shared__ float Bs[8][128];
    int tid = threadIdx.x;
    int bm = blockIdx.y << 7, bn = blockIdx.x << 7;
    int tx = tid & 15, ty = tid >> 4;
    int lrow = tid >> 1, lk4 = (tid & 1) << 2;
    const float* Ap = A  + (long)(bm + lrow)*K;
    const float* Bp = Bm + (long)(bn + lrow)*K;

    float acc[8][8];
    #pragma unroll
    for (int i = 0; i < 8; i++)
        #pragma unroll
        for (int j = 0; j < 8; j++) acc[i][j] = 0.f;

    for (int k0 = 0; k0 < K; k0 += 8) {
        float4 av = make_float4(0.f,0.f,0.f,0.f);
        float4 bv = make_float4(0.f,0.f,0.f,0.f);
        if (k0 + lk4 + 4 <= K) {
            av = *(const float4*)(Ap + k0 + lk4);
            bv = *(const float4*)(Bp + k0 + lk4);
        }
        As[lk4+0][lrow]=av.x; As[lk4+1][lrow]=av.y; As[lk4+2][lrow]=av.z; As[lk4+3][lrow]=av.w;
        Bs[lk4+0][lrow]=bv.x; Bs[lk4+1][lrow]=bv.y; Bs[lk4+2][lrow]=bv.z; Bs[lk4+3][lrow]=bv.w;
        __syncthreads();

        #pragma unroll
        for (int k = 0; k < 8; k++) {
            float4 a0 = *(const float4*)&As[k][ty<<3];
            float4 a1 = *(const float4*)&As[k][(ty<<3)+4];
            float4 b0 = *(const float4*)&Bs[k][tx<<3];
            float4 b1 = *(const float4*)&Bs[k][(tx<<3)+4];
            float rm[8] = {a0.x,a0.y,a0.z,a0.w,a1.x,a1.y,a1.z,a1.w};
            float rn[8] = {b0.x,b0.y,b0.z,b0.w,b1.x,b1.y,b1.z,b1.w};
            #pragma unroll
            for (int i = 0; i < 8; i++)
                #pragma unroll
                for (int j = 0; j < 8; j++)
                    acc[i][j] += rm[i]*rn[j];
        }
        __syncthreads();
    }

    int n0 = bn + (tx<<3);
    float4 bias0 = *(const float4*)&bias[n0];
    float4 bias1 = *(const float4*)&bias[n0+4];
    #pragma unroll
    for (int i = 0; i < 8; i++) {
        long m = bm + (ty<<3) + i;
        float4 v0, v1;
        v0.x = acc[i][0]+bias0.x; v0.y = acc[i][1]+bias0.y;
        v0.z = acc[i][2]+bias0.z; v0.w = acc[i][3]+bias0.w;
        v1.x = acc[i][4]+bias1.x; v1.y = acc[i][5]+bias1.y;
        v1.z = acc[i][6]+bias1.z; v1.w = acc[i][7]+bias1.w;
        *(float4*)&C[m*N + n0]     = v0;
        *(float4*)&C[m*N + n0 + 4] = v1;
    }
}

// ============================================================
// zero init
// ============================================================
__global__ void zero_kernel(float* p, int n)
{
    int i = blockIdx.x*blockDim.x + threadIdx.x;
    if (i < n) p[i] = 0.f;
}

// ============================================================
// Persistent GRU (one launch = all 128 timesteps).
// f32x2 inner loop.  Inter-step sync = distributed flag barrier
// with RELEASE store / ACQUIRE poll (morally-strong, same pattern
// as cooperative-groups grid.sync):
//   producer: __syncthreads -> tid0 st.release.gpu to own slot
//   consumer: 128 threads ld.acquire.gpu poll the 128 slots,
//             then __syncthreads propagates ordering to the block.
// Generations monotone across launches & graph replays.
// ============================================================
#define GRU_SMEM_FLOATS (24*1024 + 16*1028 + 3*8*16)
#define GRU_SMEM_BYTES  (GRU_SMEM_FLOATS*4)

__global__ void __launch_bounds__(256, 1) gru_persistent(
    const float* __restrict__ xg,    // [B,T,3H]
    const float* __restrict__ Whh,   // [3H,H]
    const float* __restrict__ bhh,   // [3H]
    float* hb0,                      // initial h lives here
    float* hb1,                      // ping-pong partner
    __half* __restrict__ ysh,        // [B,T,H] fp16 hi or null
    __half* __restrict__ ysl)        // fp16 lo or null
{
    extern __shared__ float sm[];
    float* w_s = sm;                        // [24][1024]
    float* h_s = sm + 24*1024;              // [16][1028] padded
    float* red = sm + 24*1024 + 16*1028;    // [24][16]

    const int tid = threadIdx.x;
    const int b  = tid & 15;
    const int jl = (tid >> 4) & 7;
    const int kh = tid >> 7;
    const int jbase = blockIdx.x << 3;
    const int j = jbase + jl;

    // base generation: all flags equal at launch entry (previous launch
    // finished all steps; zero-initialized on first run)
    unsigned base;
    asm volatile("ld.global.acquire.gpu.u32 %0, [%1];"
                 : "=r"(base) : "l"(&g_flags[blockIdx.x]));

    // load this block's Whh slice once (float4)
    for (int i4 = tid; i4 < 24*256; i4 += 256) {
        int i = i4 << 2;
        int r = i >> 10, k = i & 1023;
        int g = r >> 3, jj = r & 7;
        *(float4*)&w_s[i] =
            *(const float4*)&Whh[((size_t)(g << 10) + jbase + jj)*H_ + k];
    }
    __syncthreads();

    const float* cur = hb0;
    float* nxt = hb1;
    float bh_r = bhh[j], bh_z = bhh[H_ + j], bh_n = bhh[2*H_ + j];

    for (int t = 0; t < T_; ++t) {
        // prefetch this step's xg gate values early (cold DRAM — hide
        // latency behind h staging + the FMA loop)
        float xr = 0.f, xz = 0.f, xn = 0.f;
        if (!kh) {
            size_t xb = ((size_t)(b << 7) + t) * (3*H_);
            xr = __ldg(&xg[xb + j]);
            xz = __ldg(&xg[xb + H_ + j]);
            xn = __ldg(&xg[xb + 2*H_ + j]);
        }

        // stage h into SMEM (bypass L1 — produced by other blocks)
        for (int i4 = tid; i4 < 16*256; i4 += 256) {
            int i = i4 << 2;
            int bb = i >> 10, k = i & 1023;
            float4 v = __ldcg((const float4*)&cur[(bb << 10) + k]);
            *(float4*)&h_s[bb*1028 + k] = v;
        }
        __syncthreads();

        u64 ar2 = 0ull, az2 = 0ull, an2 = 0ull;
        const float* hp = &h_s[b*1028 + (kh << 9)];
        const float* w0 = &w_s[((      jl) << 10) + (kh << 9)];
        const float* w1 = &w_s[(( 8 + jl) << 10) + (kh << 9)];
        const float* w2 = &w_s[((16 + jl) << 10) + (kh << 9)];
        #pragma unroll 4
        for (int k = 0; k < 512; k += 4) {
            ulonglong2 hv = *(const ulonglong2*)(hp + k);
            ulonglong2 x0 = *(const ulonglong2*)(w0 + k);
            ulonglong2 x1 = *(const ulonglong2*)(w1 + k);
            ulonglong2 x2 = *(const ulonglong2*)(w2 + k);
            ar2 = fma2(hv.x, x0.x, ar2); ar2 = fma2(hv.y, x0.y, ar2);
            az2 = fma2(hv.x, x1.x, az2); az2 = fma2(hv.y, x1.y, az2);
            an2 = fma2(hv.x, x2.x, an2); an2 = fma2(hv.y, x2.y, an2);
        }
        float2 fr = upk(ar2), fz = upk(az2), fn = upk(an2);
        float ar = fr.x + fr.y, az = fz.x + fz.y, an = fn.x + fn.y;

        if (kh) {
            red[(     jl)*16 + b] = ar;
            red[( 8 + jl)*16 + b] = az;
            red[(16 + jl)*16 + b] = an;
        }
        __syncthreads();
        if (!kh) {
            ar += red[(     jl)*16 + b];
            az += red[( 8 + jl)*16 + b];
            an += red[(16 + jl)*16 + b];
            float rr = 1.f/(1.f + expf(-(xr + ar + bh_r)));
            float zz = 1.f/(1.f + expf(-(xz + az + bh_z)));
            float nn = tanhf(xn + rr*(an + bh_n));
            float hold = h_s[b*1028 + j];
            float hnew = (1.f - zz)*nn + zz*hold;
            __stcg(&nxt[(b << 10) + j], hnew);
            if (ysh) {
                size_t oi = ((size_t)(b << 7) + t)*H_ + j;
                __half hh = __float2half_rn(hnew);
                ysh[oi] = hh;
                ysl[oi] = __float2half_rn(hnew - __half2float(hh));
            }
        }
        __syncthreads();   // all h writes for this step complete (block scope)

        // publish: cumulative RELEASE store of monotone generation
        unsigned target = base + (unsigned)(t + 1);
        if (tid == 0) {
            asm volatile("st.global.release.gpu.u32 [%0], %1;"
                         :: "l"(&g_flags[blockIdx.x]), "r"(target) : "memory");
        }
        // wait: 128 threads ACQUIRE-poll the 128 slots in parallel
        if (tid < 128) {
            unsigned v;
            do {
                asm volatile("ld.global.acquire.gpu.u32 %0, [%1];"
                             : "=r"(v) : "l"(&g_flags[tid]));
            } while ((int)(v - target) < 0);
        }
        __syncthreads();   // propagate acquire ordering to whole block

        float* tmp = (float*)cur; cur = nxt; nxt = tmp;
    }
}

// ============================================================
// VAE heads
// ============================================================
__global__ void heads_kernel(const float* __restrict__ hn,
    const float* __restrict__ musW, const float* __restrict__ musb,
    const float* __restrict__ varsW, const float* __restrict__ varsb,
    const float* __restrict__ mucW, const float* __restrict__ mucb,
    const float* __restrict__ varcW, const float* __restrict__ varcb,
    const float* __restrict__ eps_s, const float* __restrict__ eps_c,
    float* __restrict__ out, float* __restrict__ zin)
{
    int gw   = (blockIdx.x << 3) + (threadIdx.x >> 5);
    int lane = threadIdx.x & 31;
    int b = gw >> 8, idx = gw & 255;
    const float* h = hn + b*H_;
    const float *Wm, *Wv; float bm, bv, ee;
    if (idx < 64) {
        Wm = musW + (long)idx*H_; Wv = varsW + (long)idx*H_;
        bm = musb[idx]; bv = varsb[idx]; ee = eps_s[b*64 + idx];
    } else {
        int cc = idx - 64;
        Wm = mucW + (long)cc*H_; Wv = varcW + (long)cc*H_;
        bm = mucb[cc]; bv = varcb[cc]; ee = eps_c[b*192 + cc];
    }
    float sm = 0.f, sv = 0.f;
    for (int k = lane; k < H_; k += 32) { float hv = h[k]; sm += hv*Wm[k]; sv += hv*Wv[k]; }
    #pragma unroll
    for (int o = 16; o; o >>= 1) {
        sm += __shfl_xor_sync(0xffffffffu, sm, o);
        sv += __shfl_xor_sync(0xffffffffu, sv, o);
    }
    if (lane == 0) {
        float mu = sm + bm, lv = sv + bv;
        float samp = mu + ee * expf(0.5f*lv);
        zin[b*256 + idx] = samp;
        if (idx < 64) {
            out[OFF_MU_S  + b*64 + idx] = mu;
            out[OFF_LV_S  + b*64 + idx] = lv;
            out[OFF_STYLE + b*64 + idx] = samp;
        } else {
            int cc = idx - 64;
            out[OFF_MU_C    + b*192 + cc] = mu;
            out[OFF_LV_C    + b*192 + cc] = lv;
            out[OFF_CONTENT + b*192 + cc] = samp;
        }
    }
}

// ============================================================
// fc -> decoder initial state
// ============================================================
__global__ void fc_kernel(const float* __restrict__ fcW, const float* __restrict__ fcb,
                          const float* __restrict__ zin, float* __restrict__ h0)
{
    int gw   = (blockIdx.x << 3) + (threadIdx.x >> 5);
    int lane = threadIdx.x & 31;
    int o = gw & 1023, b = gw >> 10;
    const float* zi = zin + b*256;
    const float* w  = fcW + (long)o*256;
    float s = 0.f;
    for (int k = lane; k < 256; k += 32) s += zi[k]*w[k];
    #pragma unroll
    for (int off = 16; off; off >>= 1) s += __shfl_xor_sync(0xffffffffu, s, off);
    if (lane == 0) h0[b*H_ + o] = s + fcb[o];
}

// ============================================================
// fp32 -> fp16 convert (single) for out_W
// ============================================================
__global__ void conv16_kernel(const float* __restrict__ src,
                              __half* __restrict__ dst, int n4)
{
    int i = blockIdx.x*blockDim.x + threadIdx.x;
    if (i >= n4) return;
    float4 v = ((const float4*)src)[i];
    __half2 p0, p1;
    p0.x = __float2half_rn(v.x); p0.y = __float2half_rn(v.y);
    p1.x = __float2half_rn(v.z); p1.y = __float2half_rn(v.w);
    ((__half2*)dst)[2*i]   = p0;
    ((__half2*)dst)[2*i+1] = p1;
}

// ============================================================
// Tensor-core logits GEMM (mma.sync fp16, 2-product):
//   C = Ah*B + Al*B  (A = fp16 hi+lo split, B = single fp16)
// 128x128x32 tiles, 4-stage cp.async pipeline (issue-ahead 3),
// ONE __syncthreads per k-iter, 80B-pitch SMEM rows.
// ============================================================
#define LG_STAGE_BYTES 30720           // 3 arrays * 128 rows * 80B
#define LG_SMEM_BYTES  (4*LG_STAGE_BYTES)

__device__ __forceinline__ void logits_issue_stage(
    unsigned sbase, int s, int kt, int tid, int bm, int bn,
    const __half* Ah, const __half* Al, const __half* Bh)
{
    int k0 = kt << 5;
    const __half* bases[3] = {Ah, Al, Bh};
    #pragma unroll
    for (int arr = 0; arr < 3; ++arr) {
        int rb = (arr < 2) ? bm : bn;
        #pragma unroll
        for (int c = 0; c < 2; ++c) {
            int ch = (tid << 1) + c;
            int row = ch >> 2, kc = ch & 3;
            unsigned dst = sbase + (unsigned)(s*LG_STAGE_BYTES + arr*10240 + row*80 + kc*16);
            const void* src = bases[arr] + (size_t)(rb + row)*H_ + k0 + (kc << 3);
            cpa16(dst, src);
        }
    }
}

__global__ void __launch_bounds__(256, 1) mma_logits(
    const __half* __restrict__ Ah, const __half* __restrict__ Al,
    const __half* __restrict__ Bh,
    const float* __restrict__ bias, float* __restrict__ C)
{
    extern __shared__ char smem_raw[];
    unsigned sbase = (unsigned)__cvta_generic_to_shared(smem_raw);
    const int tid  = threadIdx.x;
    const int lane = tid & 31, warp = tid >> 5;
    const int wm = warp >> 2, wn = warp & 3;     // warp tile 64(m) x 32(n)
    const int bm = blockIdx.x << 7;              // 16 m-tiles (fast axis: share B in L2)
    const int bn = blockIdx.y << 7;              // 250 n-tiles

    float acc[4][4][4];
    #pragma unroll
    for (int mf = 0; mf < 4; ++mf)
        #pragma unroll
        for (int nf = 0; nf < 4; ++nf)
            #pragma unroll
            for (int q = 0; q < 4; ++q) acc[mf][nf][q] = 0.f;

    // prologue: stages for kt = 0, 1, 2
    logits_issue_stage(sbase, 0, 0, tid, bm, bn, Ah, Al, Bh); cp_commit();
    logits_issue_stage(sbase, 1, 1, tid, bm, bn, Ah, Al, Bh); cp_commit();
    logits_issue_stage(sbase, 2, 2, tid, bm, bn, Ah, Al, Bh); cp_commit();

    int stage = 0;         // = kt % 4
    #pragma unroll 1
    for (int kt = 0; kt < 32; ++kt) {
        if (kt < 30)       asm volatile("cp.async.wait_group 2;\n");
        else if (kt == 30) asm volatile("cp.async.wait_group 1;\n");
        else               asm volatile("cp.async.wait_group 0;\n");
        __syncthreads();   // stage kt ready; stage (kt+3)%4 fully consumed

        unsigned sb = sbase + (unsigned)(stage*LG_STAGE_BYTES);
        #pragma unroll
        for (int kk = 0; kk < 2; ++kk) {
            uint32_t afh[4][4], afl[4][4], bfh[4][2];
            #pragma unroll
            for (int mf = 0; mf < 4; ++mf) {
                int r = (wm << 6) + (mf << 4) + (lane & 15);
                unsigned off = sb + (unsigned)(r*80 + (kk << 5) + ((lane >> 4) << 4));
                ldsm_x4(afh[mf], off);
                ldsm_x4(afl[mf], off + 10240);
            }
            #pragma unroll
            for (int nf = 0; nf < 4; ++nf) {
                int r = (wn << 5) + (nf << 3) + (lane & 7);
                unsigned off = sb + 20480u + (unsigned)(r*80 + (kk << 5) + (((lane >> 3) & 1) << 4));
                ldsm_x2(bfh[nf], off);
            }
            #pragma unroll
            for (int mf = 0; mf < 4; ++mf)
                #pragma unroll
                for (int nf = 0; nf < 4; ++nf)
                    mma16816h(acc[mf][nf], afh[mf], bfh[nf]);
            #pragma unroll
            for (int mf = 0; mf < 4; ++mf)
                #pragma unroll
                for (int nf = 0; nf < 4; ++nf)
                    mma16816h(acc[mf][nf], afl[mf], bfh[nf]);
        }

        if (kt + 3 < 32) {
            int ws = stage + 3; if (ws >= 4) ws -= 4;     // (kt+3) % 4
            logits_issue_stage(sbase, ws, kt + 3, tid, bm, bn, Ah, Al, Bh);
            cp_commit();
        }
        stage = (stage + 1 >= 4) ? 0 : stage + 1;
    }

    // epilogue: add bias, write fp32
    #pragma unroll
    for (int mf = 0; mf < 4; ++mf) {
        #pragma unroll
        for (int nf = 0; nf < 4; ++nf) {
            int m0 = bm + (wm << 6) + (mf << 4) + (lane >> 2);
            int n0 = bn + (wn << 5) + (nf << 3) + ((lane & 3) << 1);
            float b0 = bias[n0], b1 = bias[n0 + 1];
            float2 v0, v1;
            v0.x = acc[mf][nf][0] + b0; v0.y = acc[mf][nf][1] + b1;
            v1.x = acc[mf][nf][2] + b0; v1.y = acc[mf][nf][3] + b1;
            *(float2*)&C[(size_t)m0*V_ + n0]       = v0;
            *(float2*)&C[(size_t)(m0+8)*V_ + n0]   = v1;
        }
    }
}

// ============================================================
// launch
// ============================================================
extern "C" void kernel_launch(void* const* d_in, const int* in_sizes, int n_in,
                              void* d_out, int out_size)
{
    const int*   x        = (const int*)  d_in[0];
    const int*   sos_tok  = (const int*)  d_in[1];
    const float* eps_s    = (const float*)d_in[2];
    const float* eps_c    = (const float*)d_in[3];
    const float* emb      = (const float*)d_in[4];
    const float* ln_g     = (const float*)d_in[5];
    const float* ln_b     = (const float*)d_in[6];
    const float* enc_Wih  = (const float*)d_in[7];
    const float* enc_Whh  = (const float*)d_in[8];
    const float* enc_bih  = (const float*)d_in[9];
    const float* enc_bhh  = (const float*)d_in[10];
    const float* mus_W    = (const float*)d_in[11];
    const float* mus_b    = (const float*)d_in[12];
    const float* vars_W   = (const float*)d_in[13];
    const float* vars_b   = (const float*)d_in[14];
    const float* muc_W    = (const float*)d_in[15];
    const float* muc_b    = (const float*)d_in[16];
    const float* varc_W   = (const float*)d_in[17];
    const float* varc_b   = (const float*)d_in[18];
    const float* fc_W     = (const float*)d_in[19];
    const float* fc_b     = (const float*)d_in[20];
    const float* dec_Wih  = (const float*)d_in[21];
    const float* dec_Whh  = (const float*)d_in[22];
    const float* dec_bih  = (const float*)d_in[23];
    const float* dec_bhh  = (const float*)d_in[24];
    const float* out_W    = (const float*)d_in[25];
    const float* out_b    = (const float*)d_in[26];
    float* out = (float*)d_out;

    float *pe, *psos, *pdin, *pxge, *pxgd, *phA, *phB, *pzin;
    __half *pysh, *pysl, *pW16;
    cudaGetSymbolAddress((void**)&pe,   g_e);
    cudaGetSymbolAddress((void**)&psos, g_sos);
    cudaGetSymbolAddress((void**)&pdin, g_din);
    cudaGetSymbolAddress((void**)&pxge, g_xg_enc);
    cudaGetSymbolAddress((void**)&pxgd, g_xg_dec);
    cudaGetSymbolAddress((void**)&phA,  g_hA);
    cudaGetSymbolAddress((void**)&phB,  g_hB);
    cudaGetSymbolAddress((void**)&pzin, g_zin);
    cudaGetSymbolAddress((void**)&pysh, g_ys16h);
    cudaGetSymbolAddress((void**)&pysl, g_ys16l);
    cudaGetSymbolAddress((void**)&pW16, g_W16);

    cudaFuncSetAttribute(gru_persistent, cudaFuncAttributeMaxDynamicSharedMemorySize, GRU_SMEM_BYTES);
    cudaFuncSetAttribute(mma_logits,     cudaFuncAttributeMaxDynamicSharedMemorySize, LG_SMEM_BYTES);

    // 1) embed + layernorm (tokens + sos)
    embed_ln_kernel<<<BT_ + 1, 128>>>(x, sos_tok, emb, ln_g, ln_b, pe, psos);

    // 2) decoder input assembly + out_W fp16 conversion
    make_din_kernel<<<(BT_*E_ + 255)/256, 256>>>(pe, psos, pdin);
    conv16_kernel<<<(V_*H_/4 + 255)/256, 256>>>(out_W, pW16, V_*H_/4);

    // 3) both input-gate GEMMs in one launch
    sgemm_nt_bias2<<<dim3(3*H_/128, BT_/128, 2), 256>>>(
        pe, enc_Wih, enc_bih, pxge, pdin, dec_Wih, dec_bih, pxgd, BT_, 3*H_, E_);

    // 4) encoder GRU (persistent); h0 = 0 in phA
    zero_kernel<<<(B_*H_ + 255)/256, 256>>>(phA, B_*H_);
    gru_persistent<<<128, 256, GRU_SMEM_BYTES>>>(pxge, enc_Whh, enc_bhh, phA, phB,
                                                 nullptr, nullptr);
    // final hn lands back in phA (even step count)

    // 5) VAE heads + reparameterization
    heads_kernel<<<512, 256>>>(phA, mus_W, mus_b, vars_W, vars_b,
                               muc_W, muc_b, varc_W, varc_b,
                               eps_s, eps_c, out, pzin);

    // 6) fc -> decoder initial state (phB)
    fc_kernel<<<2048, 256>>>(fc_W, fc_b, pzin, phB);

    // 7) decoder GRU (persistent), writes ys as fp16 hi/lo directly
    gru_persistent<<<128, 256, GRU_SMEM_BYTES>>>(pxgd, dec_Whh, dec_bhh, phB, phA,
                                                 pysh, pysl);

    // 8) logits = ys @ out_W^T + out_b  via fp16 mma (2-product split)
    mma_logits<<<dim3(BT_/128, V_/128), 256, LG_SMEM_BYTES>>>(pysh, pysl, pW16, out_b, out);
}

// round 12
// speedup vs baseline: 2.1689x; 2.1689x over previous
#include <cuda_runtime.h>
#include <cuda_bf16.h>
#include <cuda_fp16.h>
#include <math.h>
#include <stdint.h>

#define B_  16
#define T_  128
#define E_  300
#define H_  1024
#define V_  32000
#define BT_ (B_*T_)

// ---- output section offsets (flattened tuple) ----
#define OFF_STYLE   65536000LL
#define OFF_CONTENT 65537024LL
#define OFF_MU_S    65540096LL
#define OFF_LV_S    65541120LL
#define OFF_MU_C    65542144LL
#define OFF_LV_C    65545216LL

// ---- scratch (device globals; no allocation allowed) ----
__device__ float g_e[BT_*E_];
__device__ float g_sos[E_];
__device__ float g_din[BT_*E_];
__device__ float g_xg_enc[BT_*3*H_];
__device__ float g_xg_dec[BT_*3*H_];
__device__ float g_zin[B_*256];

// h state as fp16 hi/lo pairs (recurrence is hi+lo = fp32-accurate)
__device__ __align__(256) __half g_hAhi[B_*H_];
__device__ __align__(256) __half g_hAlo[B_*H_];
__device__ __align__(256) __half g_hBhi[B_*H_];
__device__ __align__(256) __half g_hBlo[B_*H_];

// fp16 buffers for tensor-core logits GEMM
__device__ __align__(256) __half g_ys16h[BT_*H_];
__device__ __align__(256) __half g_W16[(size_t)V_*H_];

// global barrier state for persistent GRU (R9 centralized ticket)
__device__ unsigned g_bar_cnt;
__device__ unsigned g_bar_gen;

// ============================================================
// small PTX helpers
// ============================================================
__device__ __forceinline__ void cpa16(unsigned dst, const void* src) {
    asm volatile("cp.async.cg.shared.global [%0], [%1], 16;\n" :: "r"(dst), "l"(src));
}
__device__ __forceinline__ void cp_commit() {
    asm volatile("cp.async.commit_group;\n");
}
__device__ __forceinline__ void ldsm_x4(uint32_t* r, unsigned addr) {
    asm volatile("ldmatrix.sync.aligned.m8n8.x4.shared.b16 {%0,%1,%2,%3}, [%4];\n"
        : "=r"(r[0]), "=r"(r[1]), "=r"(r[2]), "=r"(r[3]) : "r"(addr));
}
__device__ __forceinline__ void ldsm_x2(uint32_t* r, unsigned addr) {
    asm volatile("ldmatrix.sync.aligned.m8n8.x2.shared.b16 {%0,%1}, [%2];\n"
        : "=r"(r[0]), "=r"(r[1]) : "r"(addr));
}
__device__ __forceinline__ void mma16816h(float* d, const uint32_t* a, const uint32_t* b) {
    asm volatile("mma.sync.aligned.m16n8k16.row.col.f32.f16.f16.f32 "
        "{%0,%1,%2,%3}, {%4,%5,%6,%7}, {%8,%9}, {%0,%1,%2,%3};\n"
        : "+f"(d[0]), "+f"(d[1]), "+f"(d[2]), "+f"(d[3])
        : "r"(a[0]), "r"(a[1]), "r"(a[2]), "r"(a[3]), "r"(b[0]), "r"(b[1]));
}
__device__ __forceinline__ void st_cg_u16(__half* p, __half v) {
    unsigned short u = *(unsigned short*)&v;
    asm volatile("st.global.cg.u16 [%0], %1;" :: "l"(p), "h"(u) : "memory");
}

// ============================================================
// Embedding gather + LayerNorm.  blocks 0..2047: tokens, block 2048: sos
// ============================================================
__global__ void embed_ln_kernel(const int* __restrict__ x, const int* __restrict__ sos,
                                const float* __restrict__ emb,
                                const float* __restrict__ lg, const float* __restrict__ lb,
                                float* __restrict__ e_out, float* __restrict__ sos_out)
{
    __shared__ float sv[E_];
    __shared__ float rbuf[4];
    int bt = blockIdx.x;
    int tok; float* dst;
    if (bt < BT_) { tok = x[bt]; dst = e_out + (long)bt*E_; }
    else          { tok = sos[0]; dst = sos_out; }
    const float* row = emb + (long)tok * E_;
    int tid = threadIdx.x;

    float s = 0.f;
    for (int i = tid; i < E_; i += 128) { float v = row[i]; sv[i] = v; s += v; }
    #pragma unroll
    for (int o = 16; o; o >>= 1) s += __shfl_xor_sync(0xffffffffu, s, o);
    if ((tid & 31) == 0) rbuf[tid >> 5] = s;
    __syncthreads();
    float mu = (rbuf[0]+rbuf[1]+rbuf[2]+rbuf[3]) * (1.f/(float)E_);

    float s2 = 0.f;
    for (int i = tid; i < E_; i += 128) { float d = sv[i]-mu; s2 += d*d; }
    #pragma unroll
    for (int o = 16; o; o >>= 1) s2 += __shfl_xor_sync(0xffffffffu, s2, o);
    __syncthreads();
    if ((tid & 31) == 0) rbuf[tid >> 5] = s2;
    __syncthreads();
    float var  = (rbuf[0]+rbuf[1]+rbuf[2]+rbuf[3]) * (1.f/(float)E_);
    float rstd = rsqrtf(var + 1e-5f);

    for (int i = tid; i < E_; i += 128)
        dst[i] = (sv[i]-mu)*rstd*lg[i] + lb[i];
}

// ============================================================
// dec_in assembly: dec_in[b,0]=sos_e ; dec_in[b,t]=e[b,t-1]
// ============================================================
__global__ void make_din_kernel(const float* __restrict__ e, const float* __restrict__ sos,
                                float* __restrict__ din)
{
    int i = blockIdx.x*blockDim.x + threadIdx.x;
    if (i >= BT_*E_) return;
    int bt = i / E_, c = i % E_;
    int t = bt & (T_-1);
    din[i] = (t == 0) ? sos[c] : e[(long)(bt-1)*E_ + c];
}

// ============================================================
// Batched SGEMM (fp32) for the two xg input-gate GEMMs.
// ============================================================
__global__ void __launch_bounds__(256, 1) sgemm_nt_bias2(
    const float* __restrict__ A0, const float* __restrict__ B0,
    const float* __restrict__ b0v, float* __restrict__ C0,
    const float* __restrict__ A1, const float* __restrict__ B1,
    const float* __restrict__ b1v, float* __restrict__ C1,
    int M, int N, int K)
{
    const float* A    = blockIdx.z ? A1 : A0;
    const float* Bm   = blockIdx.z ? B1 : B0;
    const float* bias = blockIdx.z ? b1v : b0v;
    float*       C    = blockIdx.z ? C1 : C0;

    __shared__ float As[8][128];
    __shared__ float Bs[8][128];
    int tid = threadIdx.x;
    int bm = blockIdx.y << 7, bn = blockIdx.x << 7;
    int tx = tid & 15, ty = tid >> 4;
    int lrow = tid >> 1, lk4 = (tid & 1) << 2;
    const float* Ap = A  + (long)(bm + lrow)*K;
    const float* Bp = Bm + (long)(bn + lrow)*K;

    float acc[8][8];
    #pragma unroll
    for (int i = 0; i < 8; i++)
        #pragma unroll
        for (int j = 0; j < 8; j++) acc[i][j] = 0.f;

    for (int k0 = 0; k0 < K; k0 += 8) {
        float4 av = make_float4(0.f,0.f,0.f,0.f);
        float4 bv = make_float4(0.f,0.f,0.f,0.f);
        if (k0 + lk4 + 4 <= K) {
            av = *(const float4*)(Ap + k0 + lk4);
            bv = *(const float4*)(Bp + k0 + lk4);
        }
        As[lk4+0][lrow]=av.x; As[lk4+1][lrow]=av.y; As[lk4+2][lrow]=av.z; As[lk4+3][lrow]=av.w;
        Bs[lk4+0][lrow]=bv.x; Bs[lk4+1][lrow]=bv.y; Bs[lk4+2][lrow]=bv.z; Bs[lk4+3][lrow]=bv.w;
        __syncthreads();

        #pragma unroll
        for (int k = 0; k < 8; k++) {
            float4 a0 = *(const float4*)&As[k][ty<<3];
            float4 a1 = *(const float4*)&As[k][(ty<<3)+4];
            float4 b0 = *(const float4*)&Bs[k][tx<<3];
            float4 b1 = *(const float4*)&Bs[k][(tx<<3)+4];
            float rm[8] = {a0.x,a0.y,a0.z,a0.w,a1.x,a1.y,a1.z,a1.w};
            float rn[8] = {b0.x,b0.y,b0.z,b0.w,b1.x,b1.y,b1.z,b1.w};
            #pragma unroll
            for (int i = 0; i < 8; i++)
                #pragma unroll
                for (int j = 0; j < 8; j++)
                    acc[i][j] += rm[i]*rn[j];
        }
        __syncthreads();
    }

    int n0 = bn + (tx<<3);
    float4 bias0 = *(const float4*)&bias[n0];
    float4 bias1 = *(const float4*)&bias[n0+4];
    #pragma unroll
    for (int i = 0; i < 8; i++) {
        long m = bm + (ty<<3) + i;
        float4 v0, v1;
        v0.x = acc[i][0]+bias0.x; v0.y = acc[i][1]+bias0.y;
        v0.z = acc[i][2]+bias0.z; v0.w = acc[i][3]+bias0.w;
        v1.x = acc[i][4]+bias1.x; v1.y = acc[i][5]+bias1.y;
        v1.z = acc[i][6]+bias1.z; v1.w = acc[i][7]+bias1.w;
        *(float4*)&C[m*N + n0]     = v0;
        *(float4*)&C[m*N + n0 + 4] = v1;
    }
}

// ============================================================
// zero init for encoder h0 (both half arrays)
// ============================================================
__global__ void zero_h_kernel(__half* a, __half* b)
{
    int i = blockIdx.x*blockDim.x + threadIdx.x;   // uint32 words
    if (i < 8192)       ((unsigned*)a)[i] = 0u;
    else if (i < 16384) ((unsigned*)b)[i - 8192] = 0u;
}

// ============================================================
// Persistent GRU with tensor-core mat-vec (one launch = 128 steps).
//   gh = h @ Whh^T via mma.sync m16n8k16, 3-product fp16 hi/lo split
//   (h and Whh both split; error ~1e-6 per step).
// Per block: 24 W rows (3 gates x 8 j) as fp16 hi/lo in SMEM;
// h staged per step as fp16 hi/lo from global; 8 warps split K;
// cross-warp reduce in SMEM; gates on 128 threads.
// Inter-step sync: R9 centralized ticket barrier (proven).
// ============================================================
#define GW_HI   0                     // W hi: 24 rows x 2064B
#define GW_LO   49536                 // W lo
#define GH_HI   99072                 // h hi: 16 rows x 2064B
#define GH_LO   132096                // h lo
#define GRED    165120                // partials: 8w x 3g x 16b x 8jl f32
#define GGHS    177408                // reduced gh: 384 f32
#define GRU_SMEM_BYTES 179200

__global__ void __launch_bounds__(256, 1) gru_persistent_tc(
    const float* __restrict__ xg,    // [B,T,3H]
    const float* __restrict__ Whh,   // [3H,H]
    const float* __restrict__ bhh,   // [3H]
    const __half* hi0, const __half* lo0,   // h in (ping)
    __half* hi1, __half* lo1,               // h out (pong)
    __half* __restrict__ ysh)        // [B,T,H] fp16 ys or null
{
    extern __shared__ char smc[];
    unsigned sbu = (unsigned)__cvta_generic_to_shared(smc);
    __shared__ unsigned s_gen;

    const int tid  = threadIdx.x;
    const int wid  = tid >> 5;
    const int lane = tid & 31;
    const int jbase = blockIdx.x << 3;

    // ---- setup: stage this block's W slice as fp16 hi/lo (pitch 2064B) ----
    for (int i = tid; i < 24*256; i += 256) {          // float4 granules
        int r24 = i >> 8, k4 = (i & 255) << 2;
        int g = r24 >> 3, jj = r24 & 7;
        float4 w = *(const float4*)&Whh[((size_t)(g << 10) + jbase + jj)*H_ + k4];
        __half h0 = __float2half_rn(w.x), h1 = __float2half_rn(w.y);
        __half h2 = __float2half_rn(w.z), h3 = __float2half_rn(w.w);
        __half l0 = __float2half_rn(w.x - __half2float(h0));
        __half l1 = __float2half_rn(w.y - __half2float(h1));
        __half l2 = __float2half_rn(w.z - __half2float(h2));
        __half l3 = __float2half_rn(w.w - __half2float(h3));
        char* hp = smc + GW_HI + r24*2064 + k4*2;
        char* lp = smc + GW_LO + r24*2064 + k4*2;
        *(__half2*)(hp)     = __halves2half2(h0, h1);
        *(__half2*)(hp + 4) = __halves2half2(h2, h3);
        *(__half2*)(lp)     = __halves2half2(l0, l1);
        *(__half2*)(lp + 4) = __halves2half2(l2, l3);
    }
    if (tid == 0) s_gen = atomicAdd(&g_bar_gen, 0u);
    __syncthreads();
    unsigned gen = s_gen;

    const __half* curhi = hi0; const __half* curlo = lo0;
    __half* nxthi = hi1;       __half* nxtlo = lo1;

    const int b  = tid & 15;          // for gate threads (tid<128)
    const int jl = tid >> 4;          // 0..7 when tid<128
    const int j  = jbase + (jl & 7);
    float bh_r = bhh[j], bh_z = bhh[H_ + j], bh_n = bhh[2*H_ + j];

    float* redf = (float*)(smc + GRED);
    float* ghs  = (float*)(smc + GGHS);
    const __half* his = (const __half*)(smc + GH_HI);
    const __half* los = (const __half*)(smc + GH_LO);

    for (int t = 0; t < T_; ++t) {
        // prefetch xg gate values (hide DRAM latency behind staging+mma)
        float xr = 0.f, xz = 0.f, xn = 0.f;
        if (tid < 128) {
            size_t xb = ((size_t)(b << 7) + t) * (3*H_);
            xr = __ldg(&xg[xb + j]);
            xz = __ldg(&xg[xb + H_ + j]);
            xn = __ldg(&xg[xb + 2*H_ + j]);
        }

        // stage h hi/lo into SMEM (L2 broadcast, bypass L1)
        for (int i = tid; i < 2048; i += 256) {        // uint4 = 8 halves
            int bb = i >> 7, k8 = i & 127;
            uint4 vh = __ldcg((const uint4*)curhi + i);
            uint4 vl = __ldcg((const uint4*)curlo + i);
            *(uint4*)(smc + GH_HI + bb*2064 + k8*16) = vh;
            *(uint4*)(smc + GH_LO + bb*2064 + k8*16) = vl;
        }
        __syncthreads();

        // mma: each warp owns k-slice [wid*128, wid*128+128)
        float acc[3][4];
        #pragma unroll
        for (int g = 0; g < 3; ++g)
            #pragma unroll
            for (int q = 0; q < 4; ++q) acc[g][q] = 0.f;

        const unsigned a_row = (unsigned)((lane & 15)*2064 + ((lane >> 4) << 4));
        const unsigned b_row = (unsigned)((lane & 7)*2064 + (((lane >> 3) & 1) << 4));
        const unsigned kslice = (unsigned)(wid << 8);   // wid*256 bytes

        #pragma unroll
        for (int ks = 0; ks < 8; ++ks) {
            uint32_t ah[4], al[4];
            unsigned aoff = sbu + GH_HI + a_row + kslice + (unsigned)(ks << 5);
            ldsm_x4(ah, aoff);
            ldsm_x4(al, aoff + (GH_LO - GH_HI));
            #pragma unroll
            for (int g = 0; g < 3; ++g) {
                uint32_t bh2[2], bl2[2];
                unsigned boff = sbu + GW_HI + (unsigned)(g*8*2064) + b_row
                              + kslice + (unsigned)(ks << 5);
                ldsm_x2(bh2, boff);
                ldsm_x2(bl2, boff + (GW_LO - GW_HI));
                mma16816h(acc[g], ah, bh2);
                mma16816h(acc[g], ah, bl2);
                mma16816h(acc[g], al, bh2);
            }
        }

        // store partials: D[b][jl] fragment -> red[w][g][b][jl]
        {
            int b0 = lane >> 2, jl0 = (lane & 3) << 1;
            #pragma unroll
            for (int g = 0; g < 3; ++g) {
                int base = (wid*3 + g) << 4;
                redf[(base + b0)*8 + jl0]         = acc[g][0];
                redf[(base + b0)*8 + jl0 + 1]     = acc[g][1];
                redf[(base + b0 + 8)*8 + jl0]     = acc[g][2];
                redf[(base + b0 + 8)*8 + jl0 + 1] = acc[g][3];
            }
        }
        __syncthreads();

        // reduce 8 warps -> ghs[g*128 + jl*16 + b]
        for (int o = tid; o < 384; o += 256) {
            int g = o >> 7, jj = (o >> 4) & 7, bb = o & 15;
            float s = 0.f;
            #pragma unroll
            for (int w = 0; w < 8; ++w)
                s += redf[(((w*3 + g) << 4) + bb)*8 + jj];
            ghs[o] = s;
        }
        __syncthreads();

        // gates + state update (128 threads)
        if (tid < 128) {
            float ar = ghs[       (jl << 4) + b];
            float az = ghs[128 + ((jl << 4) + b)];
            float an = ghs[256 + ((jl << 4) + b)];
            float rr = 1.f/(1.f + expf(-(xr + ar + bh_r)));
            float zz = 1.f/(1.f + expf(-(xz + az + bh_z)));
            float nn = tanhf(xn + rr*(an + bh_n));
            float hold = __half2float(his[b*1032 + j]) + __half2float(los[b*1032 + j]);
            float hnew = (1.f - zz)*nn + zz*hold;
            __half hh = __float2half_rn(hnew);
            __half hl = __float2half_rn(hnew - __half2float(hh));
            st_cg_u16(&nxthi[(b << 10) + j], hh);
            st_cg_u16(&nxtlo[(b << 10) + j], hl);
            if (ysh) ysh[((size_t)(b << 7) + t)*H_ + j] = hh;
        }
        __syncthreads();

        // R9 centralized ticket barrier (proven correct + fastest)
        if (tid == 0) {
            __threadfence();
            unsigned ticket = atomicAdd(&g_bar_cnt, 1u);
            if (ticket == 127u) {
                atomicExch(&g_bar_cnt, 0u);
                __threadfence();
                atomicAdd(&g_bar_gen, 1u);
            } else {
                unsigned cg;
                do {
                    asm volatile("ld.global.cg.u32 %0, [%1];" : "=r"(cg) : "l"(&g_bar_gen));
                    if ((int)(cg - gen) >= 1) break;
                    __nanosleep(64);
                } while (true);
                __threadfence();
            }
        }
        __syncthreads();
        ++gen;

        const __half* th = curhi; curhi = nxthi; nxthi = (__half*)th;
        const __half* tl = curlo; curlo = nxtlo; nxtlo = (__half*)tl;
    }
}

// ============================================================
// VAE heads (reads hn as fp16 hi/lo)
// ============================================================
__global__ void heads_kernel(const __half* __restrict__ hhi, const __half* __restrict__ hlo,
    const float* __restrict__ musW, const float* __restrict__ musb,
    const float* __restrict__ varsW, const float* __restrict__ varsb,
    const float* __restrict__ mucW, const float* __restrict__ mucb,
    const float* __restrict__ varcW, const float* __restrict__ varcb,
    const float* __restrict__ eps_s, const float* __restrict__ eps_c,
    float* __restrict__ out, float* __restrict__ zin)
{
    int gw   = (blockIdx.x << 3) + (threadIdx.x >> 5);
    int lane = threadIdx.x & 31;
    int b = gw >> 8, idx = gw & 255;
    const __half* hh = hhi + b*H_;
    const __half* hl = hlo + b*H_;
    const float *Wm, *Wv; float bm, bv, ee;
    if (idx < 64) {
        Wm = musW + (long)idx*H_; Wv = varsW + (long)idx*H_;
        bm = musb[idx]; bv = varsb[idx]; ee = eps_s[b*64 + idx];
    } else {
        int cc = idx - 64;
        Wm = mucW + (long)cc*H_; Wv = varcW + (long)cc*H_;
        bm = mucb[cc]; bv = varcb[cc]; ee = eps_c[b*192 + cc];
    }
    float sm = 0.f, sv = 0.f;
    for (int k = lane; k < H_; k += 32) {
        float hv = __half2float(hh[k]) + __half2float(hl[k]);
        sm += hv*Wm[k]; sv += hv*Wv[k];
    }
    #pragma unroll
    for (int o = 16; o; o >>= 1) {
        sm += __shfl_xor_sync(0xffffffffu, sm, o);
        sv += __shfl_xor_sync(0xffffffffu, sv, o);
    }
    if (lane == 0) {
        float mu = sm + bm, lv = sv + bv;
        float samp = mu + ee * expf(0.5f*lv);
        zin[b*256 + idx] = samp;
        if (idx < 64) {
            out[OFF_MU_S  + b*64 + idx] = mu;
            out[OFF_LV_S  + b*64 + idx] = lv;
            out[OFF_STYLE + b*64 + idx] = samp;
        } else {
            int cc = idx - 64;
            out[OFF_MU_C    + b*192 + cc] = mu;
            out[OFF_LV_C    + b*192 + cc] = lv;
            out[OFF_CONTENT + b*192 + cc] = samp;
        }
    }
}

// ============================================================
// fc -> decoder initial state (writes fp16 hi/lo)
// ============================================================
__global__ void fc_kernel(const float* __restrict__ fcW, const float* __restrict__ fcb,
                          const float* __restrict__ zin,
                          __half* __restrict__ h0hi, __half* __restrict__ h0lo)
{
    int gw   = (blockIdx.x << 3) + (threadIdx.x >> 5);
    int lane = threadIdx.x & 31;
    int o = gw & 1023, b = gw >> 10;
    const float* zi = zin + b*256;
    const float* w  = fcW + (long)o*256;
    float s = 0.f;
    for (int k = lane; k < 256; k += 32) s += zi[k]*w[k];
    #pragma unroll
    for (int off = 16; off; off >>= 1) s += __shfl_xor_sync(0xffffffffu, s, off);
    if (lane == 0) {
        float v = s + fcb[o];
        __half hh = __float2half_rn(v);
        h0hi[b*H_ + o] = hh;
        h0lo[b*H_ + o] = __float2half_rn(v - __half2float(hh));
    }
}

// ============================================================
// fp32 -> fp16 convert for out_W
// ============================================================
__global__ void conv16_kernel(const float* __restrict__ src,
                              __half* __restrict__ dst, int n4)
{
    int i = blockIdx.x*blockDim.x + threadIdx.x;
    if (i >= n4) return;
    float4 v = ((const float4*)src)[i];
    __half2 p0, p1;
    p0.x = __float2half_rn(v.x); p0.y = __float2half_rn(v.y);
    p1.x = __float2half_rn(v.z); p1.y = __float2half_rn(v.w);
    ((__half2*)dst)[2*i]   = p0;
    ((__half2*)dst)[2*i+1] = p1;
}

// ============================================================
// Tensor-core logits GEMM (mma.sync fp16, SINGLE product):
//   C[2048,32000] = fp16(ys) @ fp16(W)^T + bias
// 128x128x32 tiles, 4-stage cp.async pipeline (issue-ahead 3),
// ONE __syncthreads per k-iter, 80B-pitch SMEM rows.
// ============================================================
#define LG_STAGE_BYTES 20480           // 2 arrays * 128 rows * 80B
#define LG_SMEM_BYTES  (4*LG_STAGE_BYTES)

__device__ __forceinline__ void logits_issue_stage(
    unsigned sbase, int s, int kt, int tid, int bm, int bn,
    const __half* Ah, const __half* Bh)
{
    int k0 = kt << 5;
    const __half* bases[2] = {Ah, Bh};
    #pragma unroll
    for (int arr = 0; arr < 2; ++arr) {
        int rb = (arr < 1) ? bm : bn;
        #pragma unroll
        for (int c = 0; c < 2; ++c) {
            int ch = (tid << 1) + c;
            int row = ch >> 2, kc = ch & 3;
            unsigned dst = sbase + (unsigned)(s*LG_STAGE_BYTES + arr*10240 + row*80 + kc*16);
            const void* src = bases[arr] + (size_t)(rb + row)*H_ + k0 + (kc << 3);
            cpa16(dst, src);
        }
    }
}

__global__ void __launch_bounds__(256, 1) mma_logits(
    const __half* __restrict__ Ah, const __half* __restrict__ Bh,
    const float* __restrict__ bias, float* __restrict__ C)
{
    extern __shared__ char smem_raw[];
    unsigned sbase = (unsigned)__cvta_generic_to_shared(smem_raw);
    const int tid  = threadIdx.x;
    const int lane = tid & 31, warp = tid >> 5;
    const int wm = warp >> 2, wn = warp & 3;     // warp tile 64(m) x 32(n)
    const int bm = blockIdx.x << 7;              // 16 m-tiles (fast axis: share B in L2)
    const int bn = blockIdx.y << 7;              // 250 n-tiles

    float acc[4][4][4];
    #pragma unroll
    for (int mf = 0; mf < 4; ++mf)
        #pragma unroll
        for (int nf = 0; nf < 4; ++nf)
            #pragma unroll
            for (int q = 0; q < 4; ++q) acc[mf][nf][q] = 0.f;

    logits_issue_stage(sbase, 0, 0, tid, bm, bn, Ah, Bh); cp_commit();
    logits_issue_stage(sbase, 1, 1, tid, bm, bn, Ah, Bh); cp_commit();
    logits_issue_stage(sbase, 2, 2, tid, bm, bn, Ah, Bh); cp_commit();

    int stage = 0;         // = kt % 4
    #pragma unroll 1
    for (int kt = 0; kt < 32; ++kt) {
        if (kt < 30)       asm volatile("cp.async.wait_group 2;\n");
        else if (kt == 30) asm volatile("cp.async.wait_group 1;\n");
        else               asm volatile("cp.async.wait_group 0;\n");
        __syncthreads();

        unsigned sb = sbase + (unsigned)(stage*LG_STAGE_BYTES);
        #pragma unroll
        for (int kk = 0; kk < 2; ++kk) {
            uint32_t afh[4][4], bfh[4][2];
            #pragma unroll
            for (int mf = 0; mf < 4; ++mf) {
                int r = (wm << 6) + (mf << 4) + (lane & 15);
                unsigned off = sb + (unsigned)(r*80 + (kk << 5) + ((lane >> 4) << 4));
                ldsm_x4(afh[mf], off);
            }
            #pragma unroll
            for (int nf = 0; nf < 4; ++nf) {
                int r = (wn << 5) + (nf << 3) + (lane & 7);
                unsigned off = sb + 10240u + (unsigned)(r*80 + (kk << 5) + (((lane >> 3) & 1) << 4));
                ldsm_x2(bfh[nf], off);
            }
            #pragma unroll
            for (int mf = 0; mf < 4; ++mf)
                #pragma unroll
                for (int nf = 0; nf < 4; ++nf)
                    mma16816h(acc[mf][nf], afh[mf], bfh[nf]);
        }

        if (kt + 3 < 32) {
            int ws = stage + 3; if (ws >= 4) ws -= 4;
            logits_issue_stage(sbase, ws, kt + 3, tid, bm, bn, Ah, Bh);
            cp_commit();
        }
        stage = (stage + 1 >= 4) ? 0 : stage + 1;
    }

    // epilogue: add bias, write fp32
    #pragma unroll
    for (int mf = 0; mf < 4; ++mf) {
        #pragma unroll
        for (int nf = 0; nf < 4; ++nf) {
            int m0 = bm + (wm << 6) + (mf << 4) + (lane >> 2);
            int n0 = bn + (wn << 5) + (nf << 3) + ((lane & 3) << 1);
            float b0 = bias[n0], b1 = bias[n0 + 1];
            float2 v0, v1;
            v0.x = acc[mf][nf][0] + b0; v0.y = acc[mf][nf][1] + b1;
            v1.x = acc[mf][nf][2] + b0; v1.y = acc[mf][nf][3] + b1;
            *(float2*)&C[(size_t)m0*V_ + n0]       = v0;
            *(float2*)&C[(size_t)(m0+8)*V_ + n0]   = v1;
        }
    }
}

// ============================================================
// launch
// ============================================================
extern "C" void kernel_launch(void* const* d_in, const int* in_sizes, int n_in,
                              void* d_out, int out_size)
{
    const int*   x        = (const int*)  d_in[0];
    const int*   sos_tok  = (const int*)  d_in[1];
    const float* eps_s    = (const float*)d_in[2];
    const float* eps_c    = (const float*)d_in[3];
    const float* emb      = (const float*)d_in[4];
    const float* ln_g     = (const float*)d_in[5];
    const float* ln_b     = (const float*)d_in[6];
    const float* enc_Wih  = (const float*)d_in[7];
    const float* enc_Whh  = (const float*)d_in[8];
    const float* enc_bih  = (const float*)d_in[9];
    const float* enc_bhh  = (const float*)d_in[10];
    const float* mus_W    = (const float*)d_in[11];
    const float* mus_b    = (const float*)d_in[12];
    const float* vars_W   = (const float*)d_in[13];
    const float* vars_b   = (const float*)d_in[14];
    const float* muc_W    = (const float*)d_in[15];
    const float* muc_b    = (const float*)d_in[16];
    const float* varc_W   = (const float*)d_in[17];
    const float* varc_b   = (const float*)d_in[18];
    const float* fc_W     = (const float*)d_in[19];
    const float* fc_b     = (const float*)d_in[20];
    const float* dec_Wih  = (const float*)d_in[21];
    const float* dec_Whh  = (const float*)d_in[22];
    const float* dec_bih  = (const float*)d_in[23];
    const float* dec_bhh  = (const float*)d_in[24];
    const float* out_W    = (const float*)d_in[25];
    const float* out_b    = (const float*)d_in[26];
    float* out = (float*)d_out;

    float *pe, *psos, *pdin, *pxge, *pxgd, *pzin;
    __half *pAhi, *pAlo, *pBhi, *pBlo, *pysh, *pW16;
    cudaGetSymbolAddress((void**)&pe,   g_e);
    cudaGetSymbolAddress((void**)&psos, g_sos);
    cudaGetSymbolAddress((void**)&pdin, g_din);
    cudaGetSymbolAddress((void**)&pxge, g_xg_enc);
    cudaGetSymbolAddress((void**)&pxgd, g_xg_dec);
    cudaGetSymbolAddress((void**)&pzin, g_zin);
    cudaGetSymbolAddress((void**)&pAhi, g_hAhi);
    cudaGetSymbolAddress((void**)&pAlo, g_hAlo);
    cudaGetSymbolAddress((void**)&pBhi, g_hBhi);
    cudaGetSymbolAddress((void**)&pBlo, g_hBlo);
    cudaGetSymbolAddress((void**)&pysh, g_ys16h);
    cudaGetSymbolAddress((void**)&pW16, g_W16);

    cudaFuncSetAttribute(gru_persistent_tc, cudaFuncAttributeMaxDynamicSharedMemorySize, GRU_SMEM_BYTES);
    cudaFuncSetAttribute(mma_logits,        cudaFuncAttributeMaxDynamicSharedMemorySize, LG_SMEM_BYTES);

    // 1) embed + layernorm (tokens + sos)
    embed_ln_kernel<<<BT_ + 1, 128>>>(x, sos_tok, emb, ln_g, ln_b, pe, psos);

    // 2) decoder input assembly + out_W fp16 conversion
    make_din_kernel<<<(BT_*E_ + 255)/256, 256>>>(pe, psos, pdin);
    conv16_kernel<<<(V_*H_/4 + 255)/256, 256>>>(out_W, pW16, V_*H_/4);

    // 3) both input-gate GEMMs in one launch
    sgemm_nt_bias2<<<dim3(3*H_/128, BT_/128, 2), 256>>>(
        pe, enc_Wih, enc_bih, pxge, pdin, dec_Wih, dec_bih, pxgd, BT_, 3*H_, E_);

    // 4) encoder GRU (persistent, tensor-core); h0 = 0 in A pair
    zero_h_kernel<<<64, 256>>>(pAhi, pAlo);
    gru_persistent_tc<<<128, 256, GRU_SMEM_BYTES>>>(pxge, enc_Whh, enc_bhh,
                                                    pAhi, pAlo, pBhi, pBlo, nullptr);
    // final hn lands back in A pair (even step count)

    // 5) VAE heads + reparameterization
    heads_kernel<<<512, 256>>>(pAhi, pAlo, mus_W, mus_b, vars_W, vars_b,
                               muc_W, muc_b, varc_W, varc_b,
                               eps_s, eps_c, out, pzin);

    // 6) fc -> decoder initial state (B pair)
    fc_kernel<<<2048, 256>>>(fc_W, fc_b, pzin, pBhi, pBlo);

    // 7) decoder GRU (persistent, tensor-core), writes ys fp16 directly
    gru_persistent_tc<<<128, 256, GRU_SMEM_BYTES>>>(pxgd, dec_Whh, dec_bhh,
                                                    pBhi, pBlo, pAhi, pAlo, pysh);

    // 8) logits = ys @ out_W^T + out_b  via fp16 mma (single product)
    mma_logits<<<dim3(BT_/128, V_/128), 256, LG_SMEM_BYTES>>>(pysh, pW16, out_b, out);
}

// round 13
// speedup vs baseline: 2.4801x; 1.1435x over previous
#include <cuda_runtime.h>
#include <cuda_bf16.h>
#include <cuda_fp16.h>
#include <math.h>
#include <stdint.h>

#define B_  16
#define T_  128
#define E_  300
#define EP_ 320          // padded K for xg tensor GEMM
#define H_  1024
#define V_  32000
#define BT_ (B_*T_)

// ---- output section offsets (flattened tuple) ----
#define OFF_STYLE   65536000LL
#define OFF_CONTENT 65537024LL
#define OFF_MU_S    65540096LL
#define OFF_LV_S    65541120LL
#define OFF_MU_C    65542144LL
#define OFF_LV_C    65545216LL

// ---- scratch (device globals; no allocation allowed) ----
__device__ float g_e[BT_*E_];
__device__ float g_sos[E_];
__device__ float g_din[BT_*E_];
__device__ float g_xg_enc[BT_*3*H_];
__device__ float g_xg_dec[BT_*3*H_];
__device__ float g_zin[B_*256];

// padded fp16 hi/lo inputs for xg tensor GEMM
__device__ __align__(256) __half g_eh[BT_*EP_];
__device__ __align__(256) __half g_el[BT_*EP_];
__device__ __align__(256) __half g_dinh[BT_*EP_];
__device__ __align__(256) __half g_dinl[BT_*EP_];
__device__ __align__(256) __half g_wih_eh[3*H_*EP_];
__device__ __align__(256) __half g_wih_el[3*H_*EP_];
__device__ __align__(256) __half g_wih_dh[3*H_*EP_];
__device__ __align__(256) __half g_wih_dl[3*H_*EP_];

// h state as fp16 hi/lo pairs (recurrence is hi+lo = fp32-accurate)
__device__ __align__(256) __half g_hAhi[B_*H_];
__device__ __align__(256) __half g_hAlo[B_*H_];
__device__ __align__(256) __half g_hBhi[B_*H_];
__device__ __align__(256) __half g_hBlo[B_*H_];

// fp16 buffers for tensor-core logits GEMM
__device__ __align__(256) __half g_ys16h[BT_*H_];
__device__ __align__(256) __half g_W16[(size_t)V_*H_];

// global barrier counter for persistent GRU (monotone per launch, reset between)
__device__ unsigned g_bar_gen;

// ============================================================
// small PTX helpers
// ============================================================
__device__ __forceinline__ void cpa16(unsigned dst, const void* src) {
    asm volatile("cp.async.cg.shared.global [%0], [%1], 16;\n" :: "r"(dst), "l"(src));
}
__device__ __forceinline__ void cp_commit() {
    asm volatile("cp.async.commit_group;\n");
}
__device__ __forceinline__ void ldsm_x4(uint32_t* r, unsigned addr) {
    asm volatile("ldmatrix.sync.aligned.m8n8.x4.shared.b16 {%0,%1,%2,%3}, [%4];\n"
        : "=r"(r[0]), "=r"(r[1]), "=r"(r[2]), "=r"(r[3]) : "r"(addr));
}
__device__ __forceinline__ void ldsm_x2(uint32_t* r, unsigned addr) {
    asm volatile("ldmatrix.sync.aligned.m8n8.x2.shared.b16 {%0,%1}, [%2];\n"
        : "=r"(r[0]), "=r"(r[1]) : "r"(addr));
}
__device__ __forceinline__ void mma16816h(float* d, const uint32_t* a, const uint32_t* b) {
    asm volatile("mma.sync.aligned.m16n8k16.row.col.f32.f16.f16.f32 "
        "{%0,%1,%2,%3}, {%4,%5,%6,%7}, {%8,%9}, {%0,%1,%2,%3};\n"
        : "+f"(d[0]), "+f"(d[1]), "+f"(d[2]), "+f"(d[3])
        : "r"(a[0]), "r"(a[1]), "r"(a[2]), "r"(a[3]), "r"(b[0]), "r"(b[1]));
}
__device__ __forceinline__ void st_cg_u16(__half* p, __half v) {
    unsigned short u = *(unsigned short*)&v;
    asm volatile("st.global.cg.u16 [%0], %1;" :: "l"(p), "h"(u) : "memory");
}

// ============================================================
// Embedding gather + LayerNorm.  blocks 0..2047: tokens, block 2048: sos
// ============================================================
__global__ void embed_ln_kernel(const int* __restrict__ x, const int* __restrict__ sos,
                                const float* __restrict__ emb,
                                const float* __restrict__ lg, const float* __restrict__ lb,
                                float* __restrict__ e_out, float* __restrict__ sos_out)
{
    __shared__ float sv[E_];
    __shared__ float rbuf[4];
    int bt = blockIdx.x;
    int tok; float* dst;
    if (bt < BT_) { tok = x[bt]; dst = e_out + (long)bt*E_; }
    else          { tok = sos[0]; dst = sos_out; }
    const float* row = emb + (long)tok * E_;
    int tid = threadIdx.x;

    float s = 0.f;
    for (int i = tid; i < E_; i += 128) { float v = row[i]; sv[i] = v; s += v; }
    #pragma unroll
    for (int o = 16; o; o >>= 1) s += __shfl_xor_sync(0xffffffffu, s, o);
    if ((tid & 31) == 0) rbuf[tid >> 5] = s;
    __syncthreads();
    float mu = (rbuf[0]+rbuf[1]+rbuf[2]+rbuf[3]) * (1.f/(float)E_);

    float s2 = 0.f;
    for (int i = tid; i < E_; i += 128) { float d = sv[i]-mu; s2 += d*d; }
    #pragma unroll
    for (int o = 16; o; o >>= 1) s2 += __shfl_xor_sync(0xffffffffu, s2, o);
    __syncthreads();
    if ((tid & 31) == 0) rbuf[tid >> 5] = s2;
    __syncthreads();
    float var  = (rbuf[0]+rbuf[1]+rbuf[2]+rbuf[3]) * (1.f/(float)E_);
    float rstd = rsqrtf(var + 1e-5f);

    for (int i = tid; i < E_; i += 128)
        dst[i] = (sv[i]-mu)*rstd*lg[i] + lb[i];
}

// ============================================================
// dec_in assembly: dec_in[b,0]=sos_e ; dec_in[b,t]=e[b,t-1]
// ============================================================
__global__ void make_din_kernel(const float* __restrict__ e, const float* __restrict__ sos,
                                float* __restrict__ din)
{
    int i = blockIdx.x*blockDim.x + threadIdx.x;
    if (i >= BT_*E_) return;
    int bt = i / E_, c = i % E_;
    int t = bt & (T_-1);
    din[i] = (t == 0) ? sos[c] : e[(long)(bt-1)*E_ + c];
}

// ============================================================
// fp32 [rows,300] -> padded fp16 hi/lo [rows,320] (zero tail)
// ============================================================
__global__ void split_pad_kernel(const float* __restrict__ src,
                                 __half* __restrict__ hi, __half* __restrict__ lo,
                                 int rows)
{
    int i = blockIdx.x*blockDim.x + threadIdx.x;
    if (i >= rows*EP_) return;
    int r = i / EP_, c = i - r*EP_;
    float v = (c < E_) ? src[r*E_ + c] : 0.f;
    __half h = __float2half_rn(v);
    hi[i] = h;
    lo[i] = __float2half_rn(v - __half2float(h));
}

// ============================================================
// zero init for encoder h0 (both half arrays)
// ============================================================
__global__ void zero_h_kernel(__half* a, __half* b)
{
    int i = blockIdx.x*blockDim.x + threadIdx.x;   // uint32 words
    if (i < 8192)       ((unsigned*)a)[i] = 0u;
    else if (i < 16384) ((unsigned*)b)[i - 8192] = 0u;
}

// ============================================================
// reset the GRU barrier counter (launched before each GRU)
// ============================================================
__global__ void reset_bar_kernel() { g_bar_gen = 0u; }

// ============================================================
// xg tensor GEMM (fp16 3-product, exact to ~1e-6):
//   xg[2048,3072] = A[2048,320] @ Wih[3072,320]^T + bih
//   (A and W both fp16 hi/lo split; products AhBh+AhBl+AlBh)
// 128x128x32 tiles, 3-stage cp.async pipeline (K chunks = 10),
// one __syncthreads per k-iter, 80B-pitch SMEM rows.
// blockIdx.z selects (enc, dec) problem instance.
// ============================================================
#define XG_STAGE_BYTES 40960           // 4 arrays * 128 rows * 80B
#define XG_SMEM_BYTES  (3*XG_STAGE_BYTES)
#define XG_N   (3*H_)

__device__ __forceinline__ void xg_issue_stage(
    unsigned sbase, int s, int kt, int tid, int bm, int bn,
    const __half* Ah, const __half* Al,
    const __half* Bh, const __half* Bl)
{
    int k0 = kt << 5;
    const __half* bases[4] = {Ah, Al, Bh, Bl};
    #pragma unroll
    for (int arr = 0; arr < 4; ++arr) {
        int rb = (arr < 2) ? bm : bn;
        #pragma unroll
        for (int c = 0; c < 2; ++c) {
            int ch = (tid << 1) + c;
            int row = ch >> 2, kc = ch & 3;
            unsigned dst = sbase + (unsigned)(s*XG_STAGE_BYTES + arr*10240 + row*80 + kc*16);
            const void* src = bases[arr] + (size_t)(rb + row)*EP_ + k0 + (kc << 3);
            cpa16(dst, src);
        }
    }
}

__global__ void __launch_bounds__(256, 1) mma_xg(
    const __half* __restrict__ Aeh, const __half* __restrict__ Ael,
    const __half* __restrict__ Weh, const __half* __restrict__ Wel,
    const float* __restrict__ biase, float* __restrict__ Ce,
    const __half* __restrict__ Adh, const __half* __restrict__ Adl,
    const __half* __restrict__ Wdh, const __half* __restrict__ Wdl,
    const float* __restrict__ biasd, float* __restrict__ Cd)
{
    const __half* Ah = blockIdx.z ? Adh : Aeh;
    const __half* Al = blockIdx.z ? Adl : Ael;
    const __half* Bh = blockIdx.z ? Wdh : Weh;
    const __half* Bl = blockIdx.z ? Wdl : Wel;
    const float* bias = blockIdx.z ? biasd : biase;
    float* C          = blockIdx.z ? Cd : Ce;

    extern __shared__ char smem_raw[];
    unsigned sbase = (unsigned)__cvta_generic_to_shared(smem_raw);
    const int tid  = threadIdx.x;
    const int lane = tid & 31, warp = tid >> 5;
    const int wm = warp >> 2, wn = warp & 3;
    const int bm = blockIdx.x << 7;      // 16 m-tiles
    const int bn = blockIdx.y << 7;      // 24 n-tiles

    float acc[4][4][4];
    #pragma unroll
    for (int mf = 0; mf < 4; ++mf)
        #pragma unroll
        for (int nf = 0; nf < 4; ++nf)
            #pragma unroll
            for (int q = 0; q < 4; ++q) acc[mf][nf][q] = 0.f;

    xg_issue_stage(sbase, 0, 0, tid, bm, bn, Ah, Al, Bh, Bl); cp_commit();
    xg_issue_stage(sbase, 1, 1, tid, bm, bn, Ah, Al, Bh, Bl); cp_commit();

    int stage = 0;         // = kt % 3
    #pragma unroll 1
    for (int kt = 0; kt < 10; ++kt) {
        if (kt < 9) asm volatile("cp.async.wait_group 1;\n");
        else        asm volatile("cp.async.wait_group 0;\n");
        __syncthreads();

        unsigned sb = sbase + (unsigned)(stage*XG_STAGE_BYTES);
        #pragma unroll
        for (int kk = 0; kk < 2; ++kk) {
            uint32_t afh[4][4], afl[4][4], bfh[4][2], bfl[4][2];
            #pragma unroll
            for (int mf = 0; mf < 4; ++mf) {
                int r = (wm << 6) + (mf << 4) + (lane & 15);
                unsigned off = sb + (unsigned)(r*80 + (kk << 5) + ((lane >> 4) << 4));
                ldsm_x4(afh[mf], off);
                ldsm_x4(afl[mf], off + 10240);
            }
            #pragma unroll
            for (int nf = 0; nf < 4; ++nf) {
                int r = (wn << 5) + (nf << 3) + (lane & 7);
                unsigned off = sb + 20480u + (unsigned)(r*80 + (kk << 5) + (((lane >> 3) & 1) << 4));
                ldsm_x2(bfh[nf], off);
                ldsm_x2(bfl[nf], off + 10240);
            }
            #pragma unroll
            for (int mf = 0; mf < 4; ++mf)
                #pragma unroll
                for (int nf = 0; nf < 4; ++nf)
                    mma16816h(acc[mf][nf], afh[mf], bfh[nf]);
            #pragma unroll
            for (int mf = 0; mf < 4; ++mf)
                #pragma unroll
                for (int nf = 0; nf < 4; ++nf)
                    mma16816h(acc[mf][nf], afh[mf], bfl[nf]);
            #pragma unroll
            for (int mf = 0; mf < 4; ++mf)
                #pragma unroll
                for (int nf = 0; nf < 4; ++nf)
                    mma16816h(acc[mf][nf], afl[mf], bfh[nf]);
        }

        if (kt + 2 < 10) {
            int ws = (stage + 2 >= 3) ? stage - 1 : stage + 2;   // (kt+2) % 3
            xg_issue_stage(sbase, ws, kt + 2, tid, bm, bn, Ah, Al, Bh, Bl);
            cp_commit();
        }
        stage = (stage + 1 >= 3) ? 0 : stage + 1;
    }

    // epilogue: add bias, write fp32
    #pragma unroll
    for (int mf = 0; mf < 4; ++mf) {
        #pragma unroll
        for (int nf = 0; nf < 4; ++nf) {
            int m0 = bm + (wm << 6) + (mf << 4) + (lane >> 2);
            int n0 = bn + (wn << 5) + (nf << 3) + ((lane & 3) << 1);
            float b0 = bias[n0], b1 = bias[n0 + 1];
            float2 v0, v1;
            v0.x = acc[mf][nf][0] + b0; v0.y = acc[mf][nf][1] + b1;
            v1.x = acc[mf][nf][2] + b0; v1.y = acc[mf][nf][3] + b1;
            *(float2*)&C[(size_t)m0*XG_N + n0]     = v0;
            *(float2*)&C[(size_t)(m0+8)*XG_N + n0] = v1;
        }
    }
}

// ============================================================
// Persistent GRU with tensor-core mat-vec (one launch = 128 steps).
// gh = h @ Whh^T via mma.sync, 3-product fp16 hi/lo split.
// Inter-step sync: monotone RED counter barrier
//   (tid0: fence; red.add 1; poll ld.cg until >= 128*(t+1); fence)
//   counter reset to 0 by reset_bar_kernel before each launch.
// ============================================================
#define GW_HI   0                     // W hi: 24 rows x 2064B
#define GW_LO   49536                 // W lo
#define GH_HI   99072                 // h hi: 16 rows x 2064B
#define GH_LO   132096                // h lo
#define GRED    165120                // partials: 8w x 3g x 16b x 8jl f32
#define GGHS    177408                // reduced gh: 384 f32
#define GRU_SMEM_BYTES 179200

__global__ void __launch_bounds__(256, 1) gru_persistent_tc(
    const float* __restrict__ xg,    // [B,T,3H]
    const float* __restrict__ Whh,   // [3H,H]
    const float* __restrict__ bhh,   // [3H]
    const __half* hi0, const __half* lo0,   // h in (ping)
    __half* hi1, __half* lo1,               // h out (pong)
    __half* __restrict__ ysh)        // [B,T,H] fp16 ys or null
{
    extern __shared__ char smc[];
    unsigned sbu = (unsigned)__cvta_generic_to_shared(smc);

    const int tid  = threadIdx.x;
    const int wid  = tid >> 5;
    const int lane = tid & 31;
    const int jbase = blockIdx.x << 3;

    // ---- setup: stage this block's W slice as fp16 hi/lo (pitch 2064B) ----
    for (int i = tid; i < 24*256; i += 256) {          // float4 granules
        int r24 = i >> 8, k4 = (i & 255) << 2;
        int g = r24 >> 3, jj = r24 & 7;
        float4 w = *(const float4*)&Whh[((size_t)(g << 10) + jbase + jj)*H_ + k4];
        __half h0 = __float2half_rn(w.x), h1 = __float2half_rn(w.y);
        __half h2 = __float2half_rn(w.z), h3 = __float2half_rn(w.w);
        __half l0 = __float2half_rn(w.x - __half2float(h0));
        __half l1 = __float2half_rn(w.y - __half2float(h1));
        __half l2 = __float2half_rn(w.z - __half2float(h2));
        __half l3 = __float2half_rn(w.w - __half2float(h3));
        char* hp = smc + GW_HI + r24*2064 + k4*2;
        char* lp = smc + GW_LO + r24*2064 + k4*2;
        *(__half2*)(hp)     = __halves2half2(h0, h1);
        *(__half2*)(hp + 4) = __halves2half2(h2, h3);
        *(__half2*)(lp)     = __halves2half2(l0, l1);
        *(__half2*)(lp + 4) = __halves2half2(l2, l3);
    }
    __syncthreads();

    const __half* curhi = hi0; const __half* curlo = lo0;
    __half* nxthi = hi1;       __half* nxtlo = lo1;

    const int b  = tid & 15;          // for gate threads (tid<128)
    const int jl = tid >> 4;          // 0..7 when tid<128
    const int j  = jbase + (jl & 7);
    float bh_r = bhh[j], bh_z = bhh[H_ + j], bh_n = bhh[2*H_ + j];

    float* redf = (float*)(smc + GRED);
    float* ghs  = (float*)(smc + GGHS);
    const __half* his = (const __half*)(smc + GH_HI);
    const __half* los = (const __half*)(smc + GH_LO);

    for (int t = 0; t < T_; ++t) {
        // prefetch xg gate values (hide DRAM latency behind staging+mma)
        float xr = 0.f, xz = 0.f, xn = 0.f;
        if (tid < 128) {
            size_t xb = ((size_t)(b << 7) + t) * (3*H_);
            xr = __ldg(&xg[xb + j]);
            xz = __ldg(&xg[xb + H_ + j]);
            xn = __ldg(&xg[xb + 2*H_ + j]);
        }

        // stage h hi/lo into SMEM (L2 broadcast, bypass L1)
        for (int i = tid; i < 2048; i += 256) {        // uint4 = 8 halves
            int bb = i >> 7, k8 = i & 127;
            uint4 vh = __ldcg((const uint4*)curhi + i);
            uint4 vl = __ldcg((const uint4*)curlo + i);
            *(uint4*)(smc + GH_HI + bb*2064 + k8*16) = vh;
            *(uint4*)(smc + GH_LO + bb*2064 + k8*16) = vl;
        }
        __syncthreads();

        // mma: each warp owns k-slice [wid*128, wid*128+128)
        float acc[3][4];
        #pragma unroll
        for (int g = 0; g < 3; ++g)
            #pragma unroll
            for (int q = 0; q < 4; ++q) acc[g][q] = 0.f;

        const unsigned a_row = (unsigned)((lane & 15)*2064 + ((lane >> 4) << 4));
        const unsigned b_row = (unsigned)((lane & 7)*2064 + (((lane >> 3) & 1) << 4));
        const unsigned kslice = (unsigned)(wid << 8);   // wid*256 bytes

        #pragma unroll
        for (int ks = 0; ks < 8; ++ks) {
            uint32_t ah[4], al[4];
            unsigned aoff = sbu + GH_HI + a_row + kslice + (unsigned)(ks << 5);
            ldsm_x4(ah, aoff);
            ldsm_x4(al, aoff + (GH_LO - GH_HI));
            #pragma unroll
            for (int g = 0; g < 3; ++g) {
                uint32_t bh2[2], bl2[2];
                unsigned boff = sbu + GW_HI + (unsigned)(g*8*2064) + b_row
                              + kslice + (unsigned)(ks << 5);
                ldsm_x2(bh2, boff);
                ldsm_x2(bl2, boff + (GW_LO - GW_HI));
                mma16816h(acc[g], ah, bh2);
                mma16816h(acc[g], ah, bl2);
                mma16816h(acc[g], al, bh2);
            }
        }

        // store partials: D[b][jl] fragment -> red[w][g][b][jl]
        {
            int b0 = lane >> 2, jl0 = (lane & 3) << 1;
            #pragma unroll
            for (int g = 0; g < 3; ++g) {
                int base = (wid*3 + g) << 4;
                redf[(base + b0)*8 + jl0]         = acc[g][0];
                redf[(base + b0)*8 + jl0 + 1]     = acc[g][1];
                redf[(base + b0 + 8)*8 + jl0]     = acc[g][2];
                redf[(base + b0 + 8)*8 + jl0 + 1] = acc[g][3];
            }
        }
        __syncthreads();

        // reduce 8 warps -> ghs[g*128 + jl*16 + b]
        for (int o = tid; o < 384; o += 256) {
            int g = o >> 7, jj = (o >> 4) & 7, bb = o & 15;
            float s = 0.f;
            #pragma unroll
            for (int w = 0; w < 8; ++w)
                s += redf[(((w*3 + g) << 4) + bb)*8 + jj];
            ghs[o] = s;
        }
        __syncthreads();

        // gates + state update (128 threads)
        if (tid < 128) {
            float ar = ghs[       (jl << 4) + b];
            float az = ghs[128 + ((jl << 4) + b)];
            float an = ghs[256 + ((jl << 4) + b)];
            float rr = 1.f/(1.f + expf(-(xr + ar + bh_r)));
            float zz = 1.f/(1.f + expf(-(xz + az + bh_z)));
            float nn = tanhf(xn + rr*(an + bh_n));
            float hold = __half2float(his[b*1032 + j]) + __half2float(los[b*1032 + j]);
            float hnew = (1.f - zz)*nn + zz*hold;
            __half hh = __float2half_rn(hnew);
            __half hl = __float2half_rn(hnew - __half2float(hh));
            st_cg_u16(&nxthi[(b << 10) + j], hh);
            st_cg_u16(&nxtlo[(b << 10) + j], hl);
            if (ysh) ysh[((size_t)(b << 7) + t)*H_ + j] = hh;
        }
        __syncthreads();

        // grid barrier: monotone RED counter, tid0-only fence + poll
        if (t + 1 < T_) {
            unsigned target = 128u * (unsigned)(t + 1);
            if (tid == 0) {
                __threadfence();
                asm volatile("red.global.add.u32 [%0], %1;"
                             :: "l"(&g_bar_gen), "r"(1u) : "memory");
                unsigned cg;
                do {
                    asm volatile("ld.global.cg.u32 %0, [%1];" : "=r"(cg) : "l"(&g_bar_gen));
                    if ((int)(cg - target) >= 0) break;
                    __nanosleep(32);
                } while (true);
                __threadfence();
            }
            __syncthreads();
        }

        const __half* th = curhi; curhi = nxthi; nxthi = (__half*)th;
        const __half* tl = curlo; curlo = nxtlo; nxtlo = (__half*)tl;
    }
}

// ============================================================
// VAE heads (reads hn as fp16 hi/lo)
// ============================================================
__global__ void heads_kernel(const __half* __restrict__ hhi, const __half* __restrict__ hlo,
    const float* __restrict__ musW, const float* __restrict__ musb,
    const float* __restrict__ varsW, const float* __restrict__ varsb,
    const float* __restrict__ mucW, const float* __restrict__ mucb,
    const float* __restrict__ varcW, const float* __restrict__ varcb,
    const float* __restrict__ eps_s, const float* __restrict__ eps_c,
    float* __restrict__ out, float* __restrict__ zin)
{
    int gw   = (blockIdx.x << 3) + (threadIdx.x >> 5);
    int lane = threadIdx.x & 31;
    int b = gw >> 8, idx = gw & 255;
    const __half* hh = hhi + b*H_;
    const __half* hl = hlo + b*H_;
    const float *Wm, *Wv; float bm, bv, ee;
    if (idx < 64) {
        Wm = musW + (long)idx*H_; Wv = varsW + (long)idx*H_;
        bm = musb[idx]; bv = varsb[idx]; ee = eps_s[b*64 + idx];
    } else {
        int cc = idx - 64;
        Wm = mucW + (long)cc*H_; Wv = varcW + (long)cc*H_;
        bm = mucb[cc]; bv = varcb[cc]; ee = eps_c[b*192 + cc];
    }
    float sm = 0.f, sv = 0.f;
    for (int k = lane; k < H_; k += 32) {
        float hv = __half2float(hh[k]) + __half2float(hl[k]);
        sm += hv*Wm[k]; sv += hv*Wv[k];
    }
    #pragma unroll
    for (int o = 16; o; o >>= 1) {
        sm += __shfl_xor_sync(0xffffffffu, sm, o);
        sv += __shfl_xor_sync(0xffffffffu, sv, o);
    }
    if (lane == 0) {
        float mu = sm + bm, lv = sv + bv;
        float samp = mu + ee * expf(0.5f*lv);
        zin[b*256 + idx] = samp;
        if (idx < 64) {
            out[OFF_MU_S  + b*64 + idx] = mu;
            out[OFF_LV_S  + b*64 + idx] = lv;
            out[OFF_STYLE + b*64 + idx] = samp;
        } else {
            int cc = idx - 64;
            out[OFF_MU_C    + b*192 + cc] = mu;
            out[OFF_LV_C    + b*192 + cc] = lv;
            out[OFF_CONTENT + b*192 + cc] = samp;
        }
    }
}

// ============================================================
// fc -> decoder initial state (writes fp16 hi/lo)
// ============================================================
__global__ void fc_kernel(const float* __restrict__ fcW, const float* __restrict__ fcb,
                          const float* __restrict__ zin,
                          __half* __restrict__ h0hi, __half* __restrict__ h0lo)
{
    int gw   = (blockIdx.x << 3) + (threadIdx.x >> 5);
    int lane = threadIdx.x & 31;
    int o = gw & 1023, b = gw >> 10;
    const float* zi = zin + b*256;
    const float* w  = fcW + (long)o*256;
    float s = 0.f;
    for (int k = lane; k < 256; k += 32) s += zi[k]*w[k];
    #pragma unroll
    for (int off = 16; off; off >>= 1) s += __shfl_xor_sync(0xffffffffu, s, off);
    if (lane == 0) {
        float v = s + fcb[o];
        __half hh = __float2half_rn(v);
        h0hi[b*H_ + o] = hh;
        h0lo[b*H_ + o] = __float2half_rn(v - __half2float(hh));
    }
}

// ============================================================
// fp32 -> fp16 convert for out_W
// ============================================================
__global__ void conv16_kernel(const float* __restrict__ src,
                              __half* __restrict__ dst, int n4)
{
    int i = blockIdx.x*blockDim.x + threadIdx.x;
    if (i >= n4) return;
    float4 v = ((const float4*)src)[i];
    __half2 p0, p1;
    p0.x = __float2half_rn(v.x); p0.y = __float2half_rn(v.y);
    p1.x = __float2half_rn(v.z); p1.y = __float2half_rn(v.w);
    ((__half2*)dst)[2*i]   = p0;
    ((__half2*)dst)[2*i+1] = p1;
}

// ============================================================
// Tensor-core logits GEMM (mma.sync fp16, SINGLE product):
//   C[2048,32000] = fp16(ys) @ fp16(W)^T + bias
// 128x128x32 tiles, 4-stage cp.async pipeline (issue-ahead 3),
// ONE __syncthreads per k-iter, 80B-pitch SMEM rows.
// ============================================================
#define LG_STAGE_BYTES 20480           // 2 arrays * 128 rows * 80B
#define LG_SMEM_BYTES  (4*LG_STAGE_BYTES)

__device__ __forceinline__ void logits_issue_stage(
    unsigned sbase, int s, int kt, int tid, int bm, int bn,
    const __half* Ah, const __half* Bh)
{
    int k0 = kt << 5;
    const __half* bases[2] = {Ah, Bh};
    #pragma unroll
    for (int arr = 0; arr < 2; ++arr) {
        int rb = (arr < 1) ? bm : bn;
        #pragma unroll
        for (int c = 0; c < 2; ++c) {
            int ch = (tid << 1) + c;
            int row = ch >> 2, kc = ch & 3;
            unsigned dst = sbase + (unsigned)(s*LG_STAGE_BYTES + arr*10240 + row*80 + kc*16);
            const void* src = bases[arr] + (size_t)(rb + row)*H_ + k0 + (kc << 3);
            cpa16(dst, src);
        }
    }
}

__global__ void __launch_bounds__(256, 1) mma_logits(
    const __half* __restrict__ Ah, const __half* __restrict__ Bh,
    const float* __restrict__ bias, float* __restrict__ C)
{
    extern __shared__ char smem_raw[];
    unsigned sbase = (unsigned)__cvta_generic_to_shared(smem_raw);
    const int tid  = threadIdx.x;
    const int lane = tid & 31, warp = tid >> 5;
    const int wm = warp >> 2, wn = warp & 3;     // warp tile 64(m) x 32(n)
    const int bm = blockIdx.x << 7;              // 16 m-tiles (fast axis: share B in L2)
    const int bn = blockIdx.y << 7;              // 250 n-tiles

    float acc[4][4][4];
    #pragma unroll
    for (int mf = 0; mf < 4; ++mf)
        #pragma unroll
        for (int nf = 0; nf < 4; ++nf)
            #pragma unroll
            for (int q = 0; q < 4; ++q) acc[mf][nf][q] = 0.f;

    logits_issue_stage(sbase, 0, 0, tid, bm, bn, Ah, Bh); cp_commit();
    logits_issue_stage(sbase, 1, 1, tid, bm, bn, Ah, Bh); cp_commit();
    logits_issue_stage(sbase, 2, 2, tid, bm, bn, Ah, Bh); cp_commit();

    int stage = 0;         // = kt % 4
    #pragma unroll 1
    for (int kt = 0; kt < 32; ++kt) {
        if (kt < 30)       asm volatile("cp.async.wait_group 2;\n");
        else if (kt == 30) asm volatile("cp.async.wait_group 1;\n");
        else               asm volatile("cp.async.wait_group 0;\n");
        __syncthreads();

        unsigned sb = sbase + (unsigned)(stage*LG_STAGE_BYTES);
        #pragma unroll
        for (int kk = 0; kk < 2; ++kk) {
            uint32_t afh[4][4], bfh[4][2];
            #pragma unroll
            for (int mf = 0; mf < 4; ++mf) {
                int r = (wm << 6) + (mf << 4) + (lane & 15);
                unsigned off = sb + (unsigned)(r*80 + (kk << 5) + ((lane >> 4) << 4));
                ldsm_x4(afh[mf], off);
            }
            #pragma unroll
            for (int nf = 0; nf < 4; ++nf) {
                int r = (wn << 5) + (nf << 3) + (lane & 7);
                unsigned off = sb + 10240u + (unsigned)(r*80 + (kk << 5) + (((lane >> 3) & 1) << 4));
                ldsm_x2(bfh[nf], off);
            }
            #pragma unroll
            for (int mf = 0; mf < 4; ++mf)
                #pragma unroll
                for (int nf = 0; nf < 4; ++nf)
                    mma16816h(acc[mf][nf], afh[mf], bfh[nf]);
        }

        if (kt + 3 < 32) {
            int ws = stage + 3; if (ws >= 4) ws -= 4;
            logits_issue_stage(sbase, ws, kt + 3, tid, bm, bn, Ah, Bh);
            cp_commit();
        }
        stage = (stage + 1 >= 4) ? 0 : stage + 1;
    }

    // epilogue: add bias, write fp32
    #pragma unroll
    for (int mf = 0; mf < 4; ++mf) {
        #pragma unroll
        for (int nf = 0; nf < 4; ++nf) {
            int m0 = bm + (wm << 6) + (mf << 4) + (lane >> 2);
            int n0 = bn + (wn << 5) + (nf << 3) + ((lane & 3) << 1);
            float b0 = bias[n0], b1 = bias[n0 + 1];
            float2 v0, v1;
            v0.x = acc[mf][nf][0] + b0; v0.y = acc[mf][nf][1] + b1;
            v1.x = acc[mf][nf][2] + b0; v1.y = acc[mf][nf][3] + b1;
            *(float2*)&C[(size_t)m0*V_ + n0]       = v0;
            *(float2*)&C[(size_t)(m0+8)*V_ + n0]   = v1;
        }
    }
}

// ============================================================
// launch
// ============================================================
extern "C" void kernel_launch(void* const* d_in, const int* in_sizes, int n_in,
                              void* d_out, int out_size)
{
    const int*   x        = (const int*)  d_in[0];
    const int*   sos_tok  = (const int*)  d_in[1];
    const float* eps_s    = (const float*)d_in[2];
    const float* eps_c    = (const float*)d_in[3];
    const float* emb      = (const float*)d_in[4];
    const float* ln_g     = (const float*)d_in[5];
    const float* ln_b     = (const float*)d_in[6];
    const float* enc_Wih  = (const float*)d_in[7];
    const float* enc_Whh  = (const float*)d_in[8];
    const float* enc_bih  = (const float*)d_in[9];
    const float* enc_bhh  = (const float*)d_in[10];
    const float* mus_W    = (const float*)d_in[11];
    const float* mus_b    = (const float*)d_in[12];
    const float* vars_W   = (const float*)d_in[13];
    const float* vars_b   = (const float*)d_in[14];
    const float* muc_W    = (const float*)d_in[15];
    const float* muc_b    = (const float*)d_in[16];
    const float* varc_W   = (const float*)d_in[17];
    const float* varc_b   = (const float*)d_in[18];
    const float* fc_W     = (const float*)d_in[19];
    const float* fc_b     = (const float*)d_in[20];
    const float* dec_Wih  = (const float*)d_in[21];
    const float* dec_Whh  = (const float*)d_in[22];
    const float* dec_bih  = (const float*)d_in[23];
    const float* dec_bhh  = (const float*)d_in[24];
    const float* out_W    = (const float*)d_in[25];
    const float* out_b    = (const float*)d_in[26];
    float* out = (float*)d_out;

    float *pe, *psos, *pdin, *pxge, *pxgd, *pzin;
    __half *peh, *pel, *pdinh, *pdinl, *pweh, *pwel, *pwdh, *pwdl;
    __half *pAhi, *pAlo, *pBhi, *pBlo, *pysh, *pW16;
    cudaGetSymbolAddress((void**)&pe,    g_e);
    cudaGetSymbolAddress((void**)&psos,  g_sos);
    cudaGetSymbolAddress((void**)&pdin,  g_din);
    cudaGetSymbolAddress((void**)&pxge,  g_xg_enc);
    cudaGetSymbolAddress((void**)&pxgd,  g_xg_dec);
    cudaGetSymbolAddress((void**)&pzin,  g_zin);
    cudaGetSymbolAddress((void**)&peh,   g_eh);
    cudaGetSymbolAddress((void**)&pel,   g_el);
    cudaGetSymbolAddress((void**)&pdinh, g_dinh);
    cudaGetSymbolAddress((void**)&pdinl, g_dinl);
    cudaGetSymbolAddress((void**)&pweh,  g_wih_eh);
    cudaGetSymbolAddress((void**)&pwel,  g_wih_el);
    cudaGetSymbolAddress((void**)&pwdh,  g_wih_dh);
    cudaGetSymbolAddress((void**)&pwdl,  g_wih_dl);
    cudaGetSymbolAddress((void**)&pAhi,  g_hAhi);
    cudaGetSymbolAddress((void**)&pAlo,  g_hAlo);
    cudaGetSymbolAddress((void**)&pBhi,  g_hBhi);
    cudaGetSymbolAddress((void**)&pBlo,  g_hBlo);
    cudaGetSymbolAddress((void**)&pysh,  g_ys16h);
    cudaGetSymbolAddress((void**)&pW16,  g_W16);

    cudaFuncSetAttribute(gru_persistent_tc, cudaFuncAttributeMaxDynamicSharedMemorySize, GRU_SMEM_BYTES);
    cudaFuncSetAttribute(mma_logits,        cudaFuncAttributeMaxDynamicSharedMemorySize, LG_SMEM_BYTES);
    cudaFuncSetAttribute(mma_xg,            cudaFuncAttributeMaxDynamicSharedMemorySize, XG_SMEM_BYTES);

    // 1) embed + layernorm (tokens + sos)
    embed_ln_kernel<<<BT_ + 1, 128>>>(x, sos_tok, emb, ln_g, ln_b, pe, psos);

    // 2) decoder input assembly + out_W fp16 conversion
    make_din_kernel<<<(BT_*E_ + 255)/256, 256>>>(pe, psos, pdin);
    conv16_kernel<<<(V_*H_/4 + 255)/256, 256>>>(out_W, pW16, V_*H_/4);

    // 3) split/pad inputs + weights for the xg tensor GEMM
    split_pad_kernel<<<(BT_*EP_ + 255)/256, 256>>>(pe,   peh,  pel,  BT_);
    split_pad_kernel<<<(BT_*EP_ + 255)/256, 256>>>(pdin, pdinh, pdinl, BT_);
    split_pad_kernel<<<(3*H_*EP_ + 255)/256, 256>>>(enc_Wih, pweh, pwel, 3*H_);
    split_pad_kernel<<<(3*H_*EP_ + 255)/256, 256>>>(dec_Wih, pwdh, pwdl, 3*H_);

    // 4) both input-gate GEMMs on tensor cores (3-product, ~1e-6 exact)
    mma_xg<<<dim3(BT_/128, XG_N/128, 2), 256, XG_SMEM_BYTES>>>(
        peh, pel, pweh, pwel, enc_bih, pxge,
        pdinh, pdinl, pwdh, pwdl, dec_bih, pxgd);

    // 5) encoder GRU (persistent, tensor-core); h0 = 0 in A pair
    zero_h_kernel<<<64, 256>>>(pAhi, pAlo);
    reset_bar_kernel<<<1, 1>>>();
    gru_persistent_tc<<<128, 256, GRU_SMEM_BYTES>>>(pxge, enc_Whh, enc_bhh,
                                                    pAhi, pAlo, pBhi, pBlo, nullptr);
    // final hn lands back in A pair (even step count)

    // 6) VAE heads + reparameterization
    heads_kernel<<<512, 256>>>(pAhi, pAlo, mus_W, mus_b, vars_W, vars_b,
                               muc_W, muc_b, varc_W, varc_b,
                               eps_s, eps_c, out, pzin);

    // 7) fc -> decoder initial state (B pair)
    fc_kernel<<<2048, 256>>>(fc_W, fc_b, pzin, pBhi, pBlo);

    // 8) decoder GRU (persistent, tensor-core), writes ys fp16 directly
    reset_bar_kernel<<<1, 1>>>();
    gru_persistent_tc<<<128, 256, GRU_SMEM_BYTES>>>(pxgd, dec_Whh, dec_bhh,
                                                    pBhi, pBlo, pAhi, pAlo, pysh);

    // 9) logits = ys @ out_W^T + out_b  via fp16 mma (single product)
    mma_logits<<<dim3(BT_/128, V_/128), 256, LG_SMEM_BYTES>>>(pysh, pW16, out_b, out);
}

// round 16
// speedup vs baseline: 2.4988x; 1.0075x over previous
#include <cuda_runtime.h>
#include <cuda_bf16.h>
#include <cuda_fp16.h>
#include <math.h>
#include <stdint.h>

#define B_  16
#define T_  128
#define E_  300
#define EP_ 320          // padded K for xg tensor GEMM
#define H_  1024
#define V_  32000
#define BT_ (B_*T_)

// ---- output section offsets (flattened tuple) ----
#define OFF_STYLE   65536000LL
#define OFF_CONTENT 65537024LL
#define OFF_MU_S    65540096LL
#define OFF_LV_S    65541120LL
#define OFF_MU_C    65542144LL
#define OFF_LV_C    65545216LL

// ---- scratch (device globals; no allocation allowed) ----
__device__ float g_xg_enc[BT_*3*H_];
__device__ float g_xg_dec[BT_*3*H_];
__device__ float g_zin[B_*256];

// padded fp16 hi/lo inputs for xg tensor GEMM (written by fused embed_ln)
__device__ __align__(256) __half g_eh[BT_*EP_];
__device__ __align__(256) __half g_el[BT_*EP_];
__device__ __align__(256) __half g_dinh[BT_*EP_];
__device__ __align__(256) __half g_dinl[BT_*EP_];
__device__ __align__(256) __half g_wih_eh[3*H_*EP_];
__device__ __align__(256) __half g_wih_el[3*H_*EP_];
__device__ __align__(256) __half g_wih_dh[3*H_*EP_];
__device__ __align__(256) __half g_wih_dl[3*H_*EP_];

// h state as fp16 hi/lo pairs (recurrence is hi+lo = fp32-accurate)
__device__ __align__(256) __half g_hAhi[B_*H_];
__device__ __align__(256) __half g_hAlo[B_*H_];
__device__ __align__(256) __half g_hBhi[B_*H_];
__device__ __align__(256) __half g_hBlo[B_*H_];

// fp16 buffers for tensor-core logits GEMM
__device__ __align__(256) __half g_ys16h[BT_*H_];
__device__ __align__(256) __half g_W16[(size_t)V_*H_];

// global barrier counter for persistent GRU (monotone per launch, reset between)
__device__ unsigned g_bar_gen;

// ============================================================
// small PTX helpers
// ============================================================
__device__ __forceinline__ void cpa16(unsigned dst, const void* src) {
    asm volatile("cp.async.cg.shared.global [%0], [%1], 16;\n" :: "r"(dst), "l"(src));
}
__device__ __forceinline__ void cp_commit() {
    asm volatile("cp.async.commit_group;\n");
}
__device__ __forceinline__ void ldsm_x4(uint32_t* r, unsigned addr) {
    asm volatile("ldmatrix.sync.aligned.m8n8.x4.shared.b16 {%0,%1,%2,%3}, [%4];\n"
        : "=r"(r[0]), "=r"(r[1]), "=r"(r[2]), "=r"(r[3]) : "r"(addr));
}
__device__ __forceinline__ void ldsm_x2(uint32_t* r, unsigned addr) {
    asm volatile("ldmatrix.sync.aligned.m8n8.x2.shared.b16 {%0,%1}, [%2];\n"
        : "=r"(r[0]), "=r"(r[1]) : "r"(addr));
}
__device__ __forceinline__ void mma16816h(float* d, const uint32_t* a, const uint32_t* b) {
    asm volatile("mma.sync.aligned.m16n8k16.row.col.f32.f16.f16.f32 "
        "{%0,%1,%2,%3}, {%4,%5,%6,%7}, {%8,%9}, {%0,%1,%2,%3};\n"
        : "+f"(d[0]), "+f"(d[1]), "+f"(d[2]), "+f"(d[3])
        : "r"(a[0]), "r"(a[1]), "r"(a[2]), "r"(a[3]), "r"(b[0]), "r"(b[1]));
}
__device__ __forceinline__ void st_cg_u16(__half* p, __half v) {
    unsigned short u = *(unsigned short*)&v;
    asm volatile("st.global.cg.u16 [%0], %1;" :: "l"(p), "h"(u) : "memory");
}

// ============================================================
// Fused embedding gather + LayerNorm + fp16 hi/lo split + pad +
// decoder-input shift.  blocks 0..2047: tokens, block 2048: sos.
//   e row bt -> (eh, el)[bt];  if t<127 also -> (dinh, dinl)[bt+1]
//   sos row -> (dinh, dinl)[b*128] for all b
// Split values computed from the same fp32 as the old split_pad
// (bit-identical xg inputs).
// ============================================================
__global__ void embed_ln_kernel(const int* __restrict__ x, const int* __restrict__ sos,
                                const float* __restrict__ emb,
                                const float* __restrict__ lg, const float* __restrict__ lb,
                                __half* __restrict__ eh, __half* __restrict__ el,
                                __half* __restrict__ dinh, __half* __restrict__ dinl)
{
    __shared__ float sv[E_];
    __shared__ float rbuf[4];
    int bt = blockIdx.x;
    int tok = (bt < BT_) ? x[bt] : sos[0];
    const float* row = emb + (long)tok * E_;
    int tid = threadIdx.x;

    float s = 0.f;
    for (int i = tid; i < E_; i += 128) { float v = row[i]; sv[i] = v; s += v; }
    #pragma unroll
    for (int o = 16; o; o >>= 1) s += __shfl_xor_sync(0xffffffffu, s, o);
    if ((tid & 31) == 0) rbuf[tid >> 5] = s;
    __syncthreads();
    float mu = (rbuf[0]+rbuf[1]+rbuf[2]+rbuf[3]) * (1.f/(float)E_);

    float s2 = 0.f;
    for (int i = tid; i < E_; i += 128) { float d = sv[i]-mu; s2 += d*d; }
    #pragma unroll
    for (int o = 16; o; o >>= 1) s2 += __shfl_xor_sync(0xffffffffu, s2, o);
    __syncthreads();
    if ((tid & 31) == 0) rbuf[tid >> 5] = s2;
    __syncthreads();
    float var  = (rbuf[0]+rbuf[1]+rbuf[2]+rbuf[3]) * (1.f/(float)E_);
    float rstd = rsqrtf(var + 1e-5f);

    if (bt < BT_) {
        int t = bt & (T_-1);
        for (int i = tid; i < EP_; i += 128) {
            float v = (i < E_) ? (sv[i]-mu)*rstd*lg[i] + lb[i] : 0.f;
            __half h = __float2half_rn(v);
            __half l = __float2half_rn(v - __half2float(h));
            eh[(size_t)bt*EP_ + i] = h;
            el[(size_t)bt*EP_ + i] = l;
            if (t < T_-1) {
                dinh[(size_t)(bt+1)*EP_ + i] = h;
                dinl[(size_t)(bt+1)*EP_ + i] = l;
            }
        }
    } else {
        for (int i = tid; i < EP_; i += 128) {
            float v = (i < E_) ? (sv[i]-mu)*rstd*lg[i] + lb[i] : 0.f;
            __half h = __float2half_rn(v);
            __half l = __float2half_rn(v - __half2float(h));
            #pragma unroll
            for (int b = 0; b < B_; ++b) {
                dinh[(size_t)(b*T_)*EP_ + i] = h;
                dinl[(size_t)(b*T_)*EP_ + i] = l;
            }
        }
    }
}

// ============================================================
// fp32 [rows,300] -> padded fp16 hi/lo [rows,320] (weights only)
// ============================================================
__global__ void split_pad_kernel(const float* __restrict__ src,
                                 __half* __restrict__ hi, __half* __restrict__ lo,
                                 int rows)
{
    int i = blockIdx.x*blockDim.x + threadIdx.x;
    if (i >= rows*EP_) return;
    int r = i / EP_, c = i - r*EP_;
    float v = (c < E_) ? src[r*E_ + c] : 0.f;
    __half h = __float2half_rn(v);
    hi[i] = h;
    lo[i] = __float2half_rn(v - __half2float(h));
}

// ============================================================
// zero init for encoder h0 (both half arrays)
// ============================================================
__global__ void zero_h_kernel(__half* a, __half* b)
{
    int i = blockIdx.x*blockDim.x + threadIdx.x;   // uint32 words
    if (i < 8192)       ((unsigned*)a)[i] = 0u;
    else if (i < 16384) ((unsigned*)b)[i - 8192] = 0u;
}

// ============================================================
// reset the GRU barrier counter (launched before each GRU)
// ============================================================
__global__ void reset_bar_kernel() { g_bar_gen = 0u; }

// ============================================================
// xg tensor GEMM (fp16 3-product, exact to ~1e-6):
//   xg[2048,3072] = A[2048,320] @ Wih[3072,320]^T + bih
// 128x128x32 tiles, 3-stage cp.async pipeline (K chunks = 10),
// one __syncthreads per k-iter, 80B-pitch SMEM rows.
// blockIdx.z selects (enc, dec) problem instance.
// ============================================================
#define XG_STAGE_BYTES 40960           // 4 arrays * 128 rows * 80B
#define XG_SMEM_BYTES  (3*XG_STAGE_BYTES)
#define XG_N   (3*H_)

__device__ __forceinline__ void xg_issue_stage(
    unsigned sbase, int s, int kt, int tid, int bm, int bn,
    const __half* Ah, const __half* Al,
    const __half* Bh, const __half* Bl)
{
    int k0 = kt << 5;
    const __half* bases[4] = {Ah, Al, Bh, Bl};
    #pragma unroll
    for (int arr = 0; arr < 4; ++arr) {
        int rb = (arr < 2) ? bm : bn;
        #pragma unroll
        for (int c = 0; c < 2; ++c) {
            int ch = (tid << 1) + c;
            int row = ch >> 2, kc = ch & 3;
            unsigned dst = sbase + (unsigned)(s*XG_STAGE_BYTES + arr*10240 + row*80 + kc*16);
            const void* src = bases[arr] + (size_t)(rb + row)*EP_ + k0 + (kc << 3);
            cpa16(dst, src);
        }
    }
}

__global__ void __launch_bounds__(256, 1) mma_xg(
    const __half* __restrict__ Aeh, const __half* __restrict__ Ael,
    const __half* __restrict__ Weh, const __half* __restrict__ Wel,
    const float* __restrict__ biase, float* __restrict__ Ce,
    const __half* __restrict__ Adh, const __half* __restrict__ Adl,
    const __half* __restrict__ Wdh, const __half* __restrict__ Wdl,
    const float* __restrict__ biasd, float* __restrict__ Cd)
{
    const __half* Ah = blockIdx.z ? Adh : Aeh;
    const __half* Al = blockIdx.z ? Adl : Ael;
    const __half* Bh = blockIdx.z ? Wdh : Weh;
    const __half* Bl = blockIdx.z ? Wdl : Wel;
    const float* bias = blockIdx.z ? biasd : biase;
    float* C          = blockIdx.z ? Cd : Ce;

    extern __shared__ char smem_raw[];
    unsigned sbase = (unsigned)__cvta_generic_to_shared(smem_raw);
    const int tid  = threadIdx.x;
    const int lane = tid & 31, warp = tid >> 5;
    const int wm = warp >> 2, wn = warp & 3;
    const int bm = blockIdx.x << 7;      // 16 m-tiles
    const int bn = blockIdx.y << 7;      // 24 n-tiles

    float acc[4][4][4];
    #pragma unroll
    for (int mf = 0; mf < 4; ++mf)
        #pragma unroll
        for (int nf = 0; nf < 4; ++nf)
            #pragma unroll
            for (int q = 0; q < 4; ++q) acc[mf][nf][q] = 0.f;

    xg_issue_stage(sbase, 0, 0, tid, bm, bn, Ah, Al, Bh, Bl); cp_commit();
    xg_issue_stage(sbase, 1, 1, tid, bm, bn, Ah, Al, Bh, Bl); cp_commit();

    int stage = 0;         // = kt % 3
    #pragma unroll 1
    for (int kt = 0; kt < 10; ++kt) {
        if (kt < 9) asm volatile("cp.async.wait_group 1;\n");
        else        asm volatile("cp.async.wait_group 0;\n");
        __syncthreads();

        unsigned sb = sbase + (unsigned)(stage*XG_STAGE_BYTES);
        #pragma unroll
        for (int kk = 0; kk < 2; ++kk) {
            uint32_t afh[4][4], afl[4][4], bfh[4][2], bfl[4][2];
            #pragma unroll
            for (int mf = 0; mf < 4; ++mf) {
                int r = (wm << 6) + (mf << 4) + (lane & 15);
                unsigned off = sb + (unsigned)(r*80 + (kk << 5) + ((lane >> 4) << 4));
                ldsm_x4(afh[mf], off);
                ldsm_x4(afl[mf], off + 10240);
            }
            #pragma unroll
            for (int nf = 0; nf < 4; ++nf) {
                int r = (wn << 5) + (nf << 3) + (lane & 7);
                unsigned off = sb + 20480u + (unsigned)(r*80 + (kk << 5) + (((lane >> 3) & 1) << 4));
                ldsm_x2(bfh[nf], off);
                ldsm_x2(bfl[nf], off + 10240);
            }
            #pragma unroll
            for (int mf = 0; mf < 4; ++mf)
                #pragma unroll
                for (int nf = 0; nf < 4; ++nf)
                    mma16816h(acc[mf][nf], afh[mf], bfh[nf]);
            #pragma unroll
            for (int mf = 0; mf < 4; ++mf)
                #pragma unroll
                for (int nf = 0; nf < 4; ++nf)
                    mma16816h(acc[mf][nf], afh[mf], bfl[nf]);
            #pragma unroll
            for (int mf = 0; mf < 4; ++mf)
                #pragma unroll
                for (int nf = 0; nf < 4; ++nf)
                    mma16816h(acc[mf][nf], afl[mf], bfh[nf]);
        }

        if (kt + 2 < 10) {
            int ws = (stage + 2 >= 3) ? stage - 1 : stage + 2;   // (kt+2) % 3
            xg_issue_stage(sbase, ws, kt + 2, tid, bm, bn, Ah, Al, Bh, Bl);
            cp_commit();
        }
        stage = (stage + 1 >= 3) ? 0 : stage + 1;
    }

    // epilogue: add bias, write fp32
    #pragma unroll
    for (int mf = 0; mf < 4; ++mf) {
        #pragma unroll
        for (int nf = 0; nf < 4; ++nf) {
            int m0 = bm + (wm << 6) + (mf << 4) + (lane >> 2);
            int n0 = bn + (wn << 5) + (nf << 3) + ((lane & 3) << 1);
            float b0 = bias[n0], b1 = bias[n0 + 1];
            float2 v0, v1;
            v0.x = acc[mf][nf][0] + b0; v0.y = acc[mf][nf][1] + b1;
            v1.x = acc[mf][nf][2] + b0; v1.y = acc[mf][nf][3] + b1;
            *(float2*)&C[(size_t)m0*XG_N + n0]     = v0;
            *(float2*)&C[(size_t)(m0+8)*XG_N + n0] = v1;
        }
    }
}

// ============================================================
// Persistent GRU with tensor-core mat-vec (one launch = 128 steps).
// EXACT R13 version (proven): __ldcg staging, RED counter barrier
// with nanosleep poll.
// ============================================================
#define GW_HI   0                     // W hi: 24 rows x 2064B
#define GW_LO   49536                 // W lo
#define GH_HI   99072                 // h hi: 16 rows x 2064B
#define GH_LO   132096                // h lo
#define GRED    165120                // partials: 8w x 3g x 16b x 8jl f32
#define GGHS    177408                // reduced gh: 384 f32
#define GRU_SMEM_BYTES 179200

__global__ void __launch_bounds__(256, 1) gru_persistent_tc(
    const float* __restrict__ xg,    // [B,T,3H]
    const float* __restrict__ Whh,   // [3H,H]
    const float* __restrict__ bhh,   // [3H]
    const __half* hi0, const __half* lo0,   // h in (ping)
    __half* hi1, __half* lo1,               // h out (pong)
    __half* __restrict__ ysh)        // [B,T,H] fp16 ys or null
{
    extern __shared__ char smc[];
    unsigned sbu = (unsigned)__cvta_generic_to_shared(smc);

    const int tid  = threadIdx.x;
    const int wid  = tid >> 5;
    const int lane = tid & 31;
    const int jbase = blockIdx.x << 3;

    // ---- setup: stage this block's W slice as fp16 hi/lo (pitch 2064B) ----
    for (int i = tid; i < 24*256; i += 256) {          // float4 granules
        int r24 = i >> 8, k4 = (i & 255) << 2;
        int g = r24 >> 3, jj = r24 & 7;
        float4 w = *(const float4*)&Whh[((size_t)(g << 10) + jbase + jj)*H_ + k4];
        __half h0 = __float2half_rn(w.x), h1 = __float2half_rn(w.y);
        __half h2 = __float2half_rn(w.z), h3 = __float2half_rn(w.w);
        __half l0 = __float2half_rn(w.x - __half2float(h0));
        __half l1 = __float2half_rn(w.y - __half2float(h1));
        __half l2 = __float2half_rn(w.z - __half2float(h2));
        __half l3 = __float2half_rn(w.w - __half2float(h3));
        char* hp = smc + GW_HI + r24*2064 + k4*2;
        char* lp = smc + GW_LO + r24*2064 + k4*2;
        *(__half2*)(hp)     = __halves2half2(h0, h1);
        *(__half2*)(hp + 4) = __halves2half2(h2, h3);
        *(__half2*)(lp)     = __halves2half2(l0, l1);
        *(__half2*)(lp + 4) = __halves2half2(l2, l3);
    }
    __syncthreads();

    const __half* curhi = hi0; const __half* curlo = lo0;
    __half* nxthi = hi1;       __half* nxtlo = lo1;

    const int b  = tid & 15;          // for gate threads (tid<128)
    const int jl = tid >> 4;          // 0..7 when tid<128
    const int j  = jbase + (jl & 7);
    float bh_r = bhh[j], bh_z = bhh[H_ + j], bh_n = bhh[2*H_ + j];

    float* redf = (float*)(smc + GRED);
    float* ghs  = (float*)(smc + GGHS);
    const __half* his = (const __half*)(smc + GH_HI);
    const __half* los = (const __half*)(smc + GH_LO);

    for (int t = 0; t < T_; ++t) {
        // prefetch xg gate values (hide DRAM latency behind staging+mma)
        float xr = 0.f, xz = 0.f, xn = 0.f;
        if (tid < 128) {
            size_t xb = ((size_t)(b << 7) + t) * (3*H_);
            xr = __ldg(&xg[xb + j]);
            xz = __ldg(&xg[xb + H_ + j]);
            xn = __ldg(&xg[xb + 2*H_ + j]);
        }

        // stage h hi/lo into SMEM via __ldcg (generic proxy, proven)
        for (int i = tid; i < 2048; i += 256) {        // uint4 = 8 halves
            int bb = i >> 7, k8 = i & 127;
            uint4 vh = __ldcg((const uint4*)curhi + i);
            uint4 vl = __ldcg((const uint4*)curlo + i);
            *(uint4*)(smc + GH_HI + bb*2064 + k8*16) = vh;
            *(uint4*)(smc + GH_LO + bb*2064 + k8*16) = vl;
        }
        __syncthreads();

        // mma: each warp owns k-slice [wid*128, wid*128+128)
        float acc[3][4];
        #pragma unroll
        for (int g = 0; g < 3; ++g)
            #pragma unroll
            for (int q = 0; q < 4; ++q) acc[g][q] = 0.f;

        const unsigned a_row = (unsigned)((lane & 15)*2064 + ((lane >> 4) << 4));
        const unsigned b_row = (unsigned)((lane & 7)*2064 + (((lane >> 3) & 1) << 4));
        const unsigned kslice = (unsigned)(wid << 8);   // wid*256 bytes

        #pragma unroll
        for (int ks = 0; ks < 8; ++ks) {
            uint32_t ah[4], al[4];
            unsigned aoff = sbu + GH_HI + a_row + kslice + (unsigned)(ks << 5);
            ldsm_x4(ah, aoff);
            ldsm_x4(al, aoff + (GH_LO - GH_HI));
            #pragma unroll
            for (int g = 0; g < 3; ++g) {
                uint32_t bh2[2], bl2[2];
                unsigned boff = sbu + GW_HI + (unsigned)(g*8*2064) + b_row
                              + kslice + (unsigned)(ks << 5);
                ldsm_x2(bh2, boff);
                ldsm_x2(bl2, boff + (GW_LO - GW_HI));
                mma16816h(acc[g], ah, bh2);
                mma16816h(acc[g], ah, bl2);
                mma16816h(acc[g], al, bh2);
            }
        }

        // store partials: D[b][jl] fragment -> red[w][g][b][jl]
        {
            int b0 = lane >> 2, jl0 = (lane & 3) << 1;
            #pragma unroll
            for (int g = 0; g < 3; ++g) {
                int base = (wid*3 + g) << 4;
                redf[(base + b0)*8 + jl0]         = acc[g][0];
                redf[(base + b0)*8 + jl0 + 1]     = acc[g][1];
                redf[(base + b0 + 8)*8 + jl0]     = acc[g][2];
                redf[(base + b0 + 8)*8 + jl0 + 1] = acc[g][3];
            }
        }
        __syncthreads();

        // reduce 8 warps -> ghs[g*128 + jl*16 + b]
        for (int o = tid; o < 384; o += 256) {
            int g = o >> 7, jj = (o >> 4) & 7, bb = o & 15;
            float s = 0.f;
            #pragma unroll
            for (int w = 0; w < 8; ++w)
                s += redf[(((w*3 + g) << 4) + bb)*8 + jj];
            ghs[o] = s;
        }
        __syncthreads();

        // gates + state update (128 threads)
        if (tid < 128) {
            float ar = ghs[       (jl << 4) + b];
            float az = ghs[128 + ((jl << 4) + b)];
            float an = ghs[256 + ((jl << 4) + b)];
            float rr = 1.f/(1.f + expf(-(xr + ar + bh_r)));
            float zz = 1.f/(1.f + expf(-(xz + az + bh_z)));
            float nn = tanhf(xn + rr*(an + bh_n));
            float hold = __half2float(his[b*1032 + j]) + __half2float(los[b*1032 + j]);
            float hnew = (1.f - zz)*nn + zz*hold;
            __half hh = __float2half_rn(hnew);
            __half hl = __float2half_rn(hnew - __half2float(hh));
            st_cg_u16(&nxthi[(b << 10) + j], hh);
            st_cg_u16(&nxtlo[(b << 10) + j], hl);
            if (ysh) ysh[((size_t)(b << 7) + t)*H_ + j] = hh;
        }
        __syncthreads();

        // grid barrier: monotone RED counter (R13-proven, with nanosleep)
        if (t + 1 < T_) {
            unsigned target = 128u * (unsigned)(t + 1);
            if (tid == 0) {
                __threadfence();
                asm volatile("red.global.add.u32 [%0], %1;"
                             :: "l"(&g_bar_gen), "r"(1u) : "memory");
                unsigned cg;
                do {
                    asm volatile("ld.global.cg.u32 %0, [%1];" : "=r"(cg) : "l"(&g_bar_gen));
                    if ((int)(cg - target) >= 0) break;
                    __nanosleep(32);
                } while (true);
                __threadfence();
            }
            __syncthreads();
        }

        const __half* th = curhi; curhi = nxthi; nxthi = (__half*)th;
        const __half* tl = curlo; curlo = nxtlo; nxtlo = (__half*)tl;
    }
}

// ============================================================
// VAE heads (reads hn as fp16 hi/lo)
// ============================================================
__global__ void heads_kernel(const __half* __restrict__ hhi, const __half* __restrict__ hlo,
    const float* __restrict__ musW, const float* __restrict__ musb,
    const float* __restrict__ varsW, const float* __restrict__ varsb,
    const float* __restrict__ mucW, const float* __restrict__ mucb,
    const float* __restrict__ varcW, const float* __restrict__ varcb,
    const float* __restrict__ eps_s, const float* __restrict__ eps_c,
    float* __restrict__ out, float* __restrict__ zin)
{
    int gw   = (blockIdx.x << 3) + (threadIdx.x >> 5);
    int lane = threadIdx.x & 31;
    int b = gw >> 8, idx = gw & 255;
    const __half* hh = hhi + b*H_;
    const __half* hl = hlo + b*H_;
    const float *Wm, *Wv; float bm, bv, ee;
    if (idx < 64) {
        Wm = musW + (long)idx*H_; Wv = varsW + (long)idx*H_;
        bm = musb[idx]; bv = varsb[idx]; ee = eps_s[b*64 + idx];
    } else {
        int cc = idx - 64;
        Wm = mucW + (long)cc*H_; Wv = varcW + (long)cc*H_;
        bm = mucb[cc]; bv = varcb[cc]; ee = eps_c[b*192 + cc];
    }
    float sm = 0.f, sv = 0.f;
    for (int k = lane; k < H_; k += 32) {
        float hv = __half2float(hh[k]) + __half2float(hl[k]);
        sm += hv*Wm[k]; sv += hv*Wv[k];
    }
    #pragma unroll
    for (int o = 16; o; o >>= 1) {
        sm += __shfl_xor_sync(0xffffffffu, sm, o);
        sv += __shfl_xor_sync(0xffffffffu, sv, o);
    }
    if (lane == 0) {
        float mu = sm + bm, lv = sv + bv;
        float samp = mu + ee * expf(0.5f*lv);
        zin[b*256 + idx] = samp;
        if (idx < 64) {
            out[OFF_MU_S  + b*64 + idx] = mu;
            out[OFF_LV_S  + b*64 + idx] = lv;
            out[OFF_STYLE + b*64 + idx] = samp;
        } else {
            int cc = idx - 64;
            out[OFF_MU_C    + b*192 + cc] = mu;
            out[OFF_LV_C    + b*192 + cc] = lv;
            out[OFF_CONTENT + b*192 + cc] = samp;
        }
    }
}

// ============================================================
// fc -> decoder initial state (writes fp16 hi/lo)
// ============================================================
__global__ void fc_kernel(const float* __restrict__ fcW, const float* __restrict__ fcb,
                          const float* __restrict__ zin,
                          __half* __restrict__ h0hi, __half* __restrict__ h0lo)
{
    int gw   = (blockIdx.x << 3) + (threadIdx.x >> 5);
    int lane = threadIdx.x & 31;
    int o = gw & 1023, b = gw >> 10;
    const float* zi = zin + b*256;
    const float* w  = fcW + (long)o*256;
    float s = 0.f;
    for (int k = lane; k < 256; k += 32) s += zi[k]*w[k];
    #pragma unroll
    for (int off = 16; off; off >>= 1) s += __shfl_xor_sync(0xffffffffu, s, off);
    if (lane == 0) {
        float v = s + fcb[o];
        __half hh = __float2half_rn(v);
        h0hi[b*H_ + o] = hh;
        h0lo[b*H_ + o] = __float2half_rn(v - __half2float(hh));
    }
}

// ============================================================
// fp32 -> fp16 convert for out_W
// ============================================================
__global__ void conv16_kernel(const float* __restrict__ src,
                              __half* __restrict__ dst, int n4)
{
    int i = blockIdx.x*blockDim.x + threadIdx.x;
    if (i >= n4) return;
    float4 v = ((const float4*)src)[i];
    __half2 p0, p1;
    p0.x = __float2half_rn(v.x); p0.y = __float2half_rn(v.y);
    p1.x = __float2half_rn(v.z); p1.y = __float2half_rn(v.w);
    ((__half2*)dst)[2*i]   = p0;
    ((__half2*)dst)[2*i+1] = p1;
}

// ============================================================
// Tensor-core logits GEMM (mma.sync fp16, SINGLE product):
// EXACT R13 version (proven): 128x128x32 tiles, 4-stage cp.async
// pipeline (issue-ahead 3), occupancy 1, 80B-pitch SMEM rows.
// ============================================================
#define LG_STAGE_BYTES 20480           // 2 arrays * 128 rows * 80B
#define LG_SMEM_BYTES  (4*LG_STAGE_BYTES)

__device__ __forceinline__ void logits_issue_stage(
    unsigned sbase, int s, int kt, int tid, int bm, int bn,
    const __half* Ah, const __half* Bh)
{
    int k0 = kt << 5;
    const __half* bases[2] = {Ah, Bh};
    #pragma unroll
    for (int arr = 0; arr < 2; ++arr) {
        int rb = (arr < 1) ? bm : bn;
        #pragma unroll
        for (int c = 0; c < 2; ++c) {
            int ch = (tid << 1) + c;
            int row = ch >> 2, kc = ch & 3;
            unsigned dst = sbase + (unsigned)(s*LG_STAGE_BYTES + arr*10240 + row*80 + kc*16);
            const void* src = bases[arr] + (size_t)(rb + row)*H_ + k0 + (kc << 3);
            cpa16(dst, src);
        }
    }
}

__global__ void __launch_bounds__(256, 1) mma_logits(
    const __half* __restrict__ Ah, const __half* __restrict__ Bh,
    const float* __restrict__ bias, float* __restrict__ C)
{
    extern __shared__ char smem_raw[];
    unsigned sbase = (unsigned)__cvta_generic_to_shared(smem_raw);
    const int tid  = threadIdx.x;
    const int lane = tid & 31, warp = tid >> 5;
    const int wm = warp >> 2, wn = warp & 3;     // warp tile 64(m) x 32(n)
    const int bm = blockIdx.x << 7;              // 16 m-tiles (fast axis: share B in L2)
    const int bn = blockIdx.y << 7;              // 250 n-tiles

    float acc[4][4][4];
    #pragma unroll
    for (int mf = 0; mf < 4; ++mf)
        #pragma unroll
        for (int nf = 0; nf < 4; ++nf)
            #pragma unroll
            for (int q = 0; q < 4; ++q) acc[mf][nf][q] = 0.f;

    logits_issue_stage(sbase, 0, 0, tid, bm, bn, Ah, Bh); cp_commit();
    logits_issue_stage(sbase, 1, 1, tid, bm, bn, Ah, Bh); cp_commit();
    logits_issue_stage(sbase, 2, 2, tid, bm, bn, Ah, Bh); cp_commit();

    int stage = 0;         // = kt % 4
    #pragma unroll 1
    for (int kt = 0; kt < 32; ++kt) {
        if (kt < 30)       asm volatile("cp.async.wait_group 2;\n");
        else if (kt == 30) asm volatile("cp.async.wait_group 1;\n");
        else               asm volatile("cp.async.wait_group 0;\n");
        __syncthreads();

        unsigned sb = sbase + (unsigned)(stage*LG_STAGE_BYTES);
        #pragma unroll
        for (int kk = 0; kk < 2; ++kk) {
            uint32_t afh[4][4], bfh[4][2];
            #pragma unroll
            for (int mf = 0; mf < 4; ++mf) {
                int r = (wm << 6) + (mf << 4) + (lane & 15);
                unsigned off = sb + (unsigned)(r*80 + (kk << 5) + ((lane >> 4) << 4));
                ldsm_x4(afh[mf], off);
            }
            #pragma unroll
            for (int nf = 0; nf < 4; ++nf) {
                int r = (wn << 5) + (nf << 3) + (lane & 7);
                unsigned off = sb + 10240u + (unsigned)(r*80 + (kk << 5) + (((lane >> 3) & 1) << 4));
                ldsm_x2(bfh[nf], off);
            }
            #pragma unroll
            for (int mf = 0; mf < 4; ++mf)
                #pragma unroll
                for (int nf = 0; nf < 4; ++nf)
                    mma16816h(acc[mf][nf], afh[mf], bfh[nf]);
        }

        if (kt + 3 < 32) {
            int ws = stage + 3; if (ws >= 4) ws -= 4;
            logits_issue_stage(sbase, ws, kt + 3, tid, bm, bn, Ah, Bh);
            cp_commit();
        }
        stage = (stage + 1 >= 4) ? 0 : stage + 1;
    }

    // epilogue: add bias, write fp32
    #pragma unroll
    for (int mf = 0; mf < 4; ++mf) {
        #pragma unroll
        for (int nf = 0; nf < 4; ++nf) {
            int m0 = bm + (wm << 6) + (mf << 4) + (lane >> 2);
            int n0 = bn + (wn << 5) + (nf << 3) + ((lane & 3) << 1);
            float b0 = bias[n0], b1 = bias[n0 + 1];
            float2 v0, v1;
            v0.x = acc[mf][nf][0] + b0; v0.y = acc[mf][nf][1] + b1;
            v1.x = acc[mf][nf][2] + b0; v1.y = acc[mf][nf][3] + b1;
            *(float2*)&C[(size_t)m0*V_ + n0]       = v0;
            *(float2*)&C[(size_t)(m0+8)*V_ + n0]   = v1;
        }
    }
}

// ============================================================
// launch
// ============================================================
extern "C" void kernel_launch(void* const* d_in, const int* in_sizes, int n_in,
                              void* d_out, int out_size)
{
    const int*   x        = (const int*)  d_in[0];
    const int*   sos_tok  = (const int*)  d_in[1];
    const float* eps_s    = (const float*)d_in[2];
    const float* eps_c    = (const float*)d_in[3];
    const float* emb      = (const float*)d_in[4];
    const float* ln_g     = (const float*)d_in[5];
    const float* ln_b     = (const float*)d_in[6];
    const float* enc_Wih  = (const float*)d_in[7];
    const float* enc_Whh  = (const float*)d_in[8];
    const float* enc_bih  = (const float*)d_in[9];
    const float* enc_bhh  = (const float*)d_in[10];
    const float* mus_W    = (const float*)d_in[11];
    const float* mus_b    = (const float*)d_in[12];
    const float* vars_W   = (const float*)d_in[13];
    const float* vars_b   = (const float*)d_in[14];
    const float* muc_W    = (const float*)d_in[15];
    const float* muc_b    = (const float*)d_in[16];
    const float* varc_W   = (const float*)d_in[17];
    const float* varc_b   = (const float*)d_in[18];
    const float* fc_W     = (const float*)d_in[19];
    const float* fc_b     = (const float*)d_in[20];
    const float* dec_Wih  = (const float*)d_in[21];
    const float* dec_Whh  = (const float*)d_in[22];
    const float* dec_bih  = (const float*)d_in[23];
    const float* dec_bhh  = (const float*)d_in[24];
    const float* out_W    = (const float*)d_in[25];
    const float* out_b    = (const float*)d_in[26];
    float* out = (float*)d_out;

    float *pxge, *pxgd, *pzin;
    __half *peh, *pel, *pdinh, *pdinl, *pweh, *pwel, *pwdh, *pwdl;
    __half *pAhi, *pAlo, *pBhi, *pBlo, *pysh, *pW16;
    cudaGetSymbolAddress((void**)&pxge,  g_xg_enc);
    cudaGetSymbolAddress((void**)&pxgd,  g_xg_dec);
    cudaGetSymbolAddress((void**)&pzin,  g_zin);
    cudaGetSymbolAddress((void**)&peh,   g_eh);
    cudaGetSymbolAddress((void**)&pel,   g_el);
    cudaGetSymbolAddress((void**)&pdinh, g_dinh);
    cudaGetSymbolAddress((void**)&pdinl, g_dinl);
    cudaGetSymbolAddress((void**)&pweh,  g_wih_eh);
    cudaGetSymbolAddress((void**)&pwel,  g_wih_el);
    cudaGetSymbolAddress((void**)&pwdh,  g_wih_dh);
    cudaGetSymbolAddress((void**)&pwdl,  g_wih_dl);
    cudaGetSymbolAddress((void**)&pAhi,  g_hAhi);
    cudaGetSymbolAddress((void**)&pAlo,  g_hAlo);
    cudaGetSymbolAddress((void**)&pBhi,  g_hBhi);
    cudaGetSymbolAddress((void**)&pBlo,  g_hBlo);
    cudaGetSymbolAddress((void**)&pysh,  g_ys16h);
    cudaGetSymbolAddress((void**)&pW16,  g_W16);

    cudaFuncSetAttribute(gru_persistent_tc, cudaFuncAttributeMaxDynamicSharedMemorySize, GRU_SMEM_BYTES);
    cudaFuncSetAttribute(mma_logits,        cudaFuncAttributeMaxDynamicSharedMemorySize, LG_SMEM_BYTES);
    cudaFuncSetAttribute(mma_xg,            cudaFuncAttributeMaxDynamicSharedMemorySize, XG_SMEM_BYTES);

    // 1) fused embed + layernorm + fp16 hi/lo split + pad + din shift
    embed_ln_kernel<<<BT_ + 1, 128>>>(x, sos_tok, emb, ln_g, ln_b,
                                      peh, pel, pdinh, pdinl);

    // 2) out_W fp16 conversion + weight split/pads
    conv16_kernel<<<(V_*H_/4 + 255)/256, 256>>>(out_W, pW16, V_*H_/4);
    split_pad_kernel<<<(3*H_*EP_ + 255)/256, 256>>>(enc_Wih, pweh, pwel, 3*H_);
    split_pad_kernel<<<(3*H_*EP_ + 255)/256, 256>>>(dec_Wih, pwdh, pwdl, 3*H_);

    // 3) both input-gate GEMMs on tensor cores (3-product, ~1e-6 exact)
    mma_xg<<<dim3(BT_/128, XG_N/128, 2), 256, XG_SMEM_BYTES>>>(
        peh, pel, pweh, pwel, enc_bih, pxge,
        pdinh, pdinl, pwdh, pwdl, dec_bih, pxgd);

    // 4) encoder GRU (persistent, tensor-core); h0 = 0 in A pair
    zero_h_kernel<<<64, 256>>>(pAhi, pAlo);
    reset_bar_kernel<<<1, 1>>>();
    gru_persistent_tc<<<128, 256, GRU_SMEM_BYTES>>>(pxge, enc_Whh, enc_bhh,
                                                    pAhi, pAlo, pBhi, pBlo, nullptr);
    // final hn lands back in A pair (even step count)

    // 5) VAE heads + reparameterization
    heads_kernel<<<512, 256>>>(pAhi, pAlo, mus_W, mus_b, vars_W, vars_b,
                               muc_W, muc_b, varc_W, varc_b,
                               eps_s, eps_c, out, pzin);

    // 6) fc -> decoder initial state (B pair)
    fc_kernel<<<2048, 256>>>(fc_W, fc_b, pzin, pBhi, pBlo);

    // 7) decoder GRU (persistent, tensor-core), writes ys fp16 directly
    reset_bar_kernel<<<1, 1>>>();
    gru_persistent_tc<<<128, 256, GRU_SMEM_BYTES>>>(pxgd, dec_Whh, dec_bhh,
                                                    pBhi, pBlo, pAhi, pAlo, pysh);

    // 8) logits = ys @ out_W^T + out_b  via fp16 mma (single product)
    mma_logits<<<dim3(BT_/128, V_/128), 256, LG_SMEM_BYTES>>>(pysh, pW16, out_b, out);
}

// round 17
// speedup vs baseline: 2.6277x; 1.0516x over previous
#include <cuda_runtime.h>
#include <cuda_bf16.h>
#include <cuda_fp16.h>
#include <math.h>
#include <stdint.h>

#define B_  16
#define T_  128
#define E_  300
#define EP_ 320          // padded K for xg tensor GEMM
#define H_  1024
#define V_  32000
#define BT_ (B_*T_)

// ---- output section offsets (flattened tuple) ----
#define OFF_STYLE   65536000LL
#define OFF_CONTENT 65537024LL
#define OFF_MU_S    65540096LL
#define OFF_LV_S    65541120LL
#define OFF_MU_C    65542144LL
#define OFF_LV_C    65545216LL

// ---- scratch (device globals; no allocation allowed) ----
__device__ float g_xg_enc[BT_*3*H_];
__device__ float g_xg_dec[BT_*3*H_];
__device__ float g_zin[B_*256];

// padded fp16 hi/lo inputs for xg tensor GEMM (written by fused embed_ln)
__device__ __align__(256) __half g_eh[BT_*EP_];
__device__ __align__(256) __half g_el[BT_*EP_];
__device__ __align__(256) __half g_dinh[BT_*EP_];
__device__ __align__(256) __half g_dinl[BT_*EP_];
__device__ __align__(256) __half g_wih_eh[3*H_*EP_];
__device__ __align__(256) __half g_wih_el[3*H_*EP_];
__device__ __align__(256) __half g_wih_dh[3*H_*EP_];
__device__ __align__(256) __half g_wih_dl[3*H_*EP_];

// h state as fp16 hi/lo pairs (recurrence is hi+lo = fp32-accurate)
__device__ __align__(256) __half g_hAhi[B_*H_];
__device__ __align__(256) __half g_hAlo[B_*H_];
__device__ __align__(256) __half g_hBhi[B_*H_];
__device__ __align__(256) __half g_hBlo[B_*H_];

// fp16 buffers for tensor-core logits GEMM
__device__ __align__(256) __half g_ys16h[BT_*H_];
__device__ __align__(256) __half g_W16[(size_t)V_*H_];

// global barrier counter for persistent GRU (monotone per launch, reset between)
__device__ unsigned g_bar_gen;

// ============================================================
// small PTX helpers
// ============================================================
__device__ __forceinline__ void cpa16(unsigned dst, const void* src) {
    asm volatile("cp.async.cg.shared.global [%0], [%1], 16;\n" :: "r"(dst), "l"(src));
}
__device__ __forceinline__ void cp_commit() {
    asm volatile("cp.async.commit_group;\n");
}
__device__ __forceinline__ void ldsm_x4(uint32_t* r, unsigned addr) {
    asm volatile("ldmatrix.sync.aligned.m8n8.x4.shared.b16 {%0,%1,%2,%3}, [%4];\n"
        : "=r"(r[0]), "=r"(r[1]), "=r"(r[2]), "=r"(r[3]) : "r"(addr));
}
__device__ __forceinline__ void ldsm_x2(uint32_t* r, unsigned addr) {
    asm volatile("ldmatrix.sync.aligned.m8n8.x2.shared.b16 {%0,%1}, [%2];\n"
        : "=r"(r[0]), "=r"(r[1]) : "r"(addr));
}
__device__ __forceinline__ void mma16816h(float* d, const uint32_t* a, const uint32_t* b) {
    asm volatile("mma.sync.aligned.m16n8k16.row.col.f32.f16.f16.f32 "
        "{%0,%1,%2,%3}, {%4,%5,%6,%7}, {%8,%9}, {%0,%1,%2,%3};\n"
        : "+f"(d[0]), "+f"(d[1]), "+f"(d[2]), "+f"(d[3])
        : "r"(a[0]), "r"(a[1]), "r"(a[2]), "r"(a[3]), "r"(b[0]), "r"(b[1]));
}
__device__ __forceinline__ void st_cg_u16(__half* p, __half v) {
    unsigned short u = *(unsigned short*)&v;
    asm volatile("st.global.cg.u16 [%0], %1;" :: "l"(p), "h"(u) : "memory");
}

// ============================================================
// Fused embedding gather + LayerNorm + fp16 hi/lo split + pad +
// decoder-input shift.  blocks 0..2047: tokens, block 2048: sos.
// ============================================================
__global__ void embed_ln_kernel(const int* __restrict__ x, const int* __restrict__ sos,
                                const float* __restrict__ emb,
                                const float* __restrict__ lg, const float* __restrict__ lb,
                                __half* __restrict__ eh, __half* __restrict__ el,
                                __half* __restrict__ dinh, __half* __restrict__ dinl)
{
    __shared__ float sv[E_];
    __shared__ float rbuf[4];
    int bt = blockIdx.x;
    int tok = (bt < BT_) ? x[bt] : sos[0];
    const float* row = emb + (long)tok * E_;
    int tid = threadIdx.x;

    float s = 0.f;
    for (int i = tid; i < E_; i += 128) { float v = row[i]; sv[i] = v; s += v; }
    #pragma unroll
    for (int o = 16; o; o >>= 1) s += __shfl_xor_sync(0xffffffffu, s, o);
    if ((tid & 31) == 0) rbuf[tid >> 5] = s;
    __syncthreads();
    float mu = (rbuf[0]+rbuf[1]+rbuf[2]+rbuf[3]) * (1.f/(float)E_);

    float s2 = 0.f;
    for (int i = tid; i < E_; i += 128) { float d = sv[i]-mu; s2 += d*d; }
    #pragma unroll
    for (int o = 16; o; o >>= 1) s2 += __shfl_xor_sync(0xffffffffu, s2, o);
    __syncthreads();
    if ((tid & 31) == 0) rbuf[tid >> 5] = s2;
    __syncthreads();
    float var  = (rbuf[0]+rbuf[1]+rbuf[2]+rbuf[3]) * (1.f/(float)E_);
    float rstd = rsqrtf(var + 1e-5f);

    if (bt < BT_) {
        int t = bt & (T_-1);
        for (int i = tid; i < EP_; i += 128) {
            float v = (i < E_) ? (sv[i]-mu)*rstd*lg[i] + lb[i] : 0.f;
            __half h = __float2half_rn(v);
            __half l = __float2half_rn(v - __half2float(h));
            eh[(size_t)bt*EP_ + i] = h;
            el[(size_t)bt*EP_ + i] = l;
            if (t < T_-1) {
                dinh[(size_t)(bt+1)*EP_ + i] = h;
                dinl[(size_t)(bt+1)*EP_ + i] = l;
            }
        }
    } else {
        for (int i = tid; i < EP_; i += 128) {
            float v = (i < E_) ? (sv[i]-mu)*rstd*lg[i] + lb[i] : 0.f;
            __half h = __float2half_rn(v);
            __half l = __float2half_rn(v - __half2float(h));
            #pragma unroll
            for (int b = 0; b < B_; ++b) {
                dinh[(size_t)(b*T_)*EP_ + i] = h;
                dinl[(size_t)(b*T_)*EP_ + i] = l;
            }
        }
    }
}

// ============================================================
// Weight split/pad: both Wih matrices in one launch (blockIdx.z)
// ============================================================
__global__ void split_pad2_kernel(const float* __restrict__ src0,
                                  __half* __restrict__ hi0, __half* __restrict__ lo0,
                                  const float* __restrict__ src1,
                                  __half* __restrict__ hi1, __half* __restrict__ lo1,
                                  int rows)
{
    const float* src = blockIdx.z ? src1 : src0;
    __half* hi = blockIdx.z ? hi1 : hi0;
    __half* lo = blockIdx.z ? lo1 : lo0;
    int i = blockIdx.x*blockDim.x + threadIdx.x;
    if (i >= rows*EP_) return;
    int r = i / EP_, c = i - r*EP_;
    float v = (c < E_) ? src[r*E_ + c] : 0.f;
    __half h = __float2half_rn(v);
    hi[i] = h;
    lo[i] = __float2half_rn(v - __half2float(h));
}

// ============================================================
// init: zero encoder h0 (both halves) + reset barrier counter
// ============================================================
__global__ void init_enc_kernel(__half* a, __half* b)
{
    int i = blockIdx.x*blockDim.x + threadIdx.x;   // uint32 words
    if (i == 0) g_bar_gen = 0u;
    if (i < 8192)       ((unsigned*)a)[i] = 0u;
    else if (i < 16384) ((unsigned*)b)[i - 8192] = 0u;
}

// ============================================================
// reset the GRU barrier counter (before decoder GRU)
// ============================================================
__global__ void reset_bar_kernel() { g_bar_gen = 0u; }

// ============================================================
// xg tensor GEMM (fp16 3-product, exact to ~1e-6):
//   xg[2048,3072] = A[2048,320] @ Wih[3072,320]^T + bih
// 128x128x32 tiles, 3-stage cp.async pipeline (K chunks = 10),
// one __syncthreads per k-iter, 80B-pitch SMEM rows.
// blockIdx.z selects (enc, dec) problem instance.
// ============================================================
#define XG_STAGE_BYTES 40960           // 4 arrays * 128 rows * 80B
#define XG_SMEM_BYTES  (3*XG_STAGE_BYTES)
#define XG_N   (3*H_)

__device__ __forceinline__ void xg_issue_stage(
    unsigned sbase, int s, int kt, int tid, int bm, int bn,
    const __half* Ah, const __half* Al,
    const __half* Bh, const __half* Bl)
{
    int k0 = kt << 5;
    const __half* bases[4] = {Ah, Al, Bh, Bl};
    #pragma unroll
    for (int arr = 0; arr < 4; ++arr) {
        int rb = (arr < 2) ? bm : bn;
        #pragma unroll
        for (int c = 0; c < 2; ++c) {
            int ch = (tid << 1) + c;
            int row = ch >> 2, kc = ch & 3;
            unsigned dst = sbase + (unsigned)(s*XG_STAGE_BYTES + arr*10240 + row*80 + kc*16);
            const void* src = bases[arr] + (size_t)(rb + row)*EP_ + k0 + (kc << 3);
            cpa16(dst, src);
        }
    }
}

__global__ void __launch_bounds__(256, 1) mma_xg(
    const __half* __restrict__ Aeh, const __half* __restrict__ Ael,
    const __half* __restrict__ Weh, const __half* __restrict__ Wel,
    const float* __restrict__ biase, float* __restrict__ Ce,
    const __half* __restrict__ Adh, const __half* __restrict__ Adl,
    const __half* __restrict__ Wdh, const __half* __restrict__ Wdl,
    const float* __restrict__ biasd, float* __restrict__ Cd)
{
    const __half* Ah = blockIdx.z ? Adh : Aeh;
    const __half* Al = blockIdx.z ? Adl : Ael;
    const __half* Bh = blockIdx.z ? Wdh : Weh;
    const __half* Bl = blockIdx.z ? Wdl : Wel;
    const float* bias = blockIdx.z ? biasd : biase;
    float* C          = blockIdx.z ? Cd : Ce;

    extern __shared__ char smem_raw[];
    unsigned sbase = (unsigned)__cvta_generic_to_shared(smem_raw);
    const int tid  = threadIdx.x;
    const int lane = tid & 31, warp = tid >> 5;
    const int wm = warp >> 2, wn = warp & 3;
    const int bm = blockIdx.x << 7;      // 16 m-tiles
    const int bn = blockIdx.y << 7;      // 24 n-tiles

    float acc[4][4][4];
    #pragma unroll
    for (int mf = 0; mf < 4; ++mf)
        #pragma unroll
        for (int nf = 0; nf < 4; ++nf)
            #pragma unroll
            for (int q = 0; q < 4; ++q) acc[mf][nf][q] = 0.f;

    xg_issue_stage(sbase, 0, 0, tid, bm, bn, Ah, Al, Bh, Bl); cp_commit();
    xg_issue_stage(sbase, 1, 1, tid, bm, bn, Ah, Al, Bh, Bl); cp_commit();

    int stage = 0;         // = kt % 3
    #pragma unroll 1
    for (int kt = 0; kt < 10; ++kt) {
        if (kt < 9) asm volatile("cp.async.wait_group 1;\n");
        else        asm volatile("cp.async.wait_group 0;\n");
        __syncthreads();

        unsigned sb = sbase + (unsigned)(stage*XG_STAGE_BYTES);
        #pragma unroll
        for (int kk = 0; kk < 2; ++kk) {
            uint32_t afh[4][4], afl[4][4], bfh[4][2], bfl[4][2];
            #pragma unroll
            for (int mf = 0; mf < 4; ++mf) {
                int r = (wm << 6) + (mf << 4) + (lane & 15);
                unsigned off = sb + (unsigned)(r*80 + (kk << 5) + ((lane >> 4) << 4));
                ldsm_x4(afh[mf], off);
                ldsm_x4(afl[mf], off + 10240);
            }
            #pragma unroll
            for (int nf = 0; nf < 4; ++nf) {
                int r = (wn << 5) + (nf << 3) + (lane & 7);
                unsigned off = sb + 20480u + (unsigned)(r*80 + (kk << 5) + (((lane >> 3) & 1) << 4));
                ldsm_x2(bfh[nf], off);
                ldsm_x2(bfl[nf], off + 10240);
            }
            #pragma unroll
            for (int mf = 0; mf < 4; ++mf)
                #pragma unroll
                for (int nf = 0; nf < 4; ++nf)
                    mma16816h(acc[mf][nf], afh[mf], bfh[nf]);
            #pragma unroll
            for (int mf = 0; mf < 4; ++mf)
                #pragma unroll
                for (int nf = 0; nf < 4; ++nf)
                    mma16816h(acc[mf][nf], afh[mf], bfl[nf]);
            #pragma unroll
            for (int mf = 0; mf < 4; ++mf)
                #pragma unroll
                for (int nf = 0; nf < 4; ++nf)
                    mma16816h(acc[mf][nf], afl[mf], bfh[nf]);
        }

        if (kt + 2 < 10) {
            int ws = (stage + 2 >= 3) ? stage - 1 : stage + 2;   // (kt+2) % 3
            xg_issue_stage(sbase, ws, kt + 2, tid, bm, bn, Ah, Al, Bh, Bl);
            cp_commit();
        }
        stage = (stage + 1 >= 3) ? 0 : stage + 1;
    }

    // epilogue: add bias, write fp32
    #pragma unroll
    for (int mf = 0; mf < 4; ++mf) {
        #pragma unroll
        for (int nf = 0; nf < 4; ++nf) {
            int m0 = bm + (wm << 6) + (mf << 4) + (lane >> 2);
            int n0 = bn + (wn << 5) + (nf << 3) + ((lane & 3) << 1);
            float b0 = bias[n0], b1 = bias[n0 + 1];
            float2 v0, v1;
            v0.x = acc[mf][nf][0] + b0; v0.y = acc[mf][nf][1] + b1;
            v1.x = acc[mf][nf][2] + b0; v1.y = acc[mf][nf][3] + b1;
            *(float2*)&C[(size_t)m0*XG_N + n0]     = v0;
            *(float2*)&C[(size_t)(m0+8)*XG_N + n0] = v1;
        }
    }
}

// ============================================================
// Persistent GRU with tensor-core mat-vec (one launch = 128 steps).
// EXACT R13/R16 version (proven): __ldcg staging, RED counter
// barrier with nanosleep poll.
// ============================================================
#define GW_HI   0                     // W hi: 24 rows x 2064B
#define GW_LO   49536                 // W lo
#define GH_HI   99072                 // h hi: 16 rows x 2064B
#define GH_LO   132096                // h lo
#define GRED    165120                // partials: 8w x 3g x 16b x 8jl f32
#define GGHS    177408                // reduced gh: 384 f32
#define GRU_SMEM_BYTES 179200

__global__ void __launch_bounds__(256, 1) gru_persistent_tc(
    const float* __restrict__ xg,    // [B,T,3H]
    const float* __restrict__ Whh,   // [3H,H]
    const float* __restrict__ bhh,   // [3H]
    const __half* hi0, const __half* lo0,   // h in (ping)
    __half* hi1, __half* lo1,               // h out (pong)
    __half* __restrict__ ysh)        // [B,T,H] fp16 ys or null
{
    extern __shared__ char smc[];
    unsigned sbu = (unsigned)__cvta_generic_to_shared(smc);

    const int tid  = threadIdx.x;
    const int wid  = tid >> 5;
    const int lane = tid & 31;
    const int jbase = blockIdx.x << 3;

    // ---- setup: stage this block's W slice as fp16 hi/lo (pitch 2064B) ----
    for (int i = tid; i < 24*256; i += 256) {          // float4 granules
        int r24 = i >> 8, k4 = (i & 255) << 2;
        int g = r24 >> 3, jj = r24 & 7;
        float4 w = *(const float4*)&Whh[((size_t)(g << 10) + jbase + jj)*H_ + k4];
        __half h0 = __float2half_rn(w.x), h1 = __float2half_rn(w.y);
        __half h2 = __float2half_rn(w.z), h3 = __float2half_rn(w.w);
        __half l0 = __float2half_rn(w.x - __half2float(h0));
        __half l1 = __float2half_rn(w.y - __half2float(h1));
        __half l2 = __float2half_rn(w.z - __half2float(h2));
        __half l3 = __float2half_rn(w.w - __half2float(h3));
        char* hp = smc + GW_HI + r24*2064 + k4*2;
        char* lp = smc + GW_LO + r24*2064 + k4*2;
        *(__half2*)(hp)     = __halves2half2(h0, h1);
        *(__half2*)(hp + 4) = __halves2half2(h2, h3);
        *(__half2*)(lp)     = __halves2half2(l0, l1);
        *(__half2*)(lp + 4) = __halves2half2(l2, l3);
    }
    __syncthreads();

    const __half* curhi = hi0; const __half* curlo = lo0;
    __half* nxthi = hi1;       __half* nxtlo = lo1;

    const int b  = tid & 15;          // for gate threads (tid<128)
    const int jl = tid >> 4;          // 0..7 when tid<128
    const int j  = jbase + (jl & 7);
    float bh_r = bhh[j], bh_z = bhh[H_ + j], bh_n = bhh[2*H_ + j];

    float* redf = (float*)(smc + GRED);
    float* ghs  = (float*)(smc + GGHS);
    const __half* his = (const __half*)(smc + GH_HI);
    const __half* los = (const __half*)(smc + GH_LO);

    for (int t = 0; t < T_; ++t) {
        // prefetch xg gate values (hide DRAM latency behind staging+mma)
        float xr = 0.f, xz = 0.f, xn = 0.f;
        if (tid < 128) {
            size_t xb = ((size_t)(b << 7) + t) * (3*H_);
            xr = __ldg(&xg[xb + j]);
            xz = __ldg(&xg[xb + H_ + j]);
            xn = __ldg(&xg[xb + 2*H_ + j]);
        }

        // stage h hi/lo into SMEM via __ldcg (generic proxy, proven)
        for (int i = tid; i < 2048; i += 256) {        // uint4 = 8 halves
            int bb = i >> 7, k8 = i & 127;
            uint4 vh = __ldcg((const uint4*)curhi + i);
            uint4 vl = __ldcg((const uint4*)curlo + i);
            *(uint4*)(smc + GH_HI + bb*2064 + k8*16) = vh;
            *(uint4*)(smc + GH_LO + bb*2064 + k8*16) = vl;
        }
        __syncthreads();

        // mma: each warp owns k-slice [wid*128, wid*128+128)
        float acc[3][4];
        #pragma unroll
        for (int g = 0; g < 3; ++g)
            #pragma unroll
            for (int q = 0; q < 4; ++q) acc[g][q] = 0.f;

        const unsigned a_row = (unsigned)((lane & 15)*2064 + ((lane >> 4) << 4));
        const unsigned b_row = (unsigned)((lane & 7)*2064 + (((lane >> 3) & 1) << 4));
        const unsigned kslice = (unsigned)(wid << 8);   // wid*256 bytes

        #pragma unroll
        for (int ks = 0; ks < 8; ++ks) {
            uint32_t ah[4], al[4];
            unsigned aoff = sbu + GH_HI + a_row + kslice + (unsigned)(ks << 5);
            ldsm_x4(ah, aoff);
            ldsm_x4(al, aoff + (GH_LO - GH_HI));
            #pragma unroll
            for (int g = 0; g < 3; ++g) {
                uint32_t bh2[2], bl2[2];
                unsigned boff = sbu + GW_HI + (unsigned)(g*8*2064) + b_row
                              + kslice + (unsigned)(ks << 5);
                ldsm_x2(bh2, boff);
                ldsm_x2(bl2, boff + (GW_LO - GW_HI));
                mma16816h(acc[g], ah, bh2);
                mma16816h(acc[g], ah, bl2);
                mma16816h(acc[g], al, bh2);
            }
        }

        // store partials: D[b][jl] fragment -> red[w][g][b][jl]
        {
            int b0 = lane >> 2, jl0 = (lane & 3) << 1;
            #pragma unroll
            for (int g = 0; g < 3; ++g) {
                int base = (wid*3 + g) << 4;
                redf[(base + b0)*8 + jl0]         = acc[g][0];
                redf[(base + b0)*8 + jl0 + 1]     = acc[g][1];
                redf[(base + b0 + 8)*8 + jl0]     = acc[g][2];
                redf[(base + b0 + 8)*8 + jl0 + 1] = acc[g][3];
            }
        }
        __syncthreads();

        // reduce 8 warps -> ghs[g*128 + jl*16 + b]
        for (int o = tid; o < 384; o += 256) {
            int g = o >> 7, jj = (o >> 4) & 7, bb = o & 15;
            float s = 0.f;
            #pragma unroll
            for (int w = 0; w < 8; ++w)
                s += redf[(((w*3 + g) << 4) + bb)*8 + jj];
            ghs[o] = s;
        }
        __syncthreads();

        // gates + state update (128 threads)
        if (tid < 128) {
            float ar = ghs[       (jl << 4) + b];
            float az = ghs[128 + ((jl << 4) + b)];
            float an = ghs[256 + ((jl << 4) + b)];
            float rr = 1.f/(1.f + expf(-(xr + ar + bh_r)));
            float zz = 1.f/(1.f + expf(-(xz + az + bh_z)));
            float nn = tanhf(xn + rr*(an + bh_n));
            float hold = __half2float(his[b*1032 + j]) + __half2float(los[b*1032 + j]);
            float hnew = (1.f - zz)*nn + zz*hold;
            __half hh = __float2half_rn(hnew);
            __half hl = __float2half_rn(hnew - __half2float(hh));
            st_cg_u16(&nxthi[(b << 10) + j], hh);
            st_cg_u16(&nxtlo[(b << 10) + j], hl);
            if (ysh) ysh[((size_t)(b << 7) + t)*H_ + j] = hh;
        }
        __syncthreads();

        // grid barrier: monotone RED counter (R13-proven, with nanosleep)
        if (t + 1 < T_) {
            unsigned target = 128u * (unsigned)(t + 1);
            if (tid == 0) {
                __threadfence();
                asm volatile("red.global.add.u32 [%0], %1;"
                             :: "l"(&g_bar_gen), "r"(1u) : "memory");
                unsigned cg;
                do {
                    asm volatile("ld.global.cg.u32 %0, [%1];" : "=r"(cg) : "l"(&g_bar_gen));
                    if ((int)(cg - target) >= 0) break;
                    __nanosleep(32);
                } while (true);
                __threadfence();
            }
            __syncthreads();
        }

        const __half* th = curhi; curhi = nxthi; nxthi = (__half*)th;
        const __half* tl = curlo; curlo = nxtlo; nxtlo = (__half*)tl;
    }
}

// ============================================================
// VAE heads (reads hn as fp16 hi/lo)
// ============================================================
__global__ void heads_kernel(const __half* __restrict__ hhi, const __half* __restrict__ hlo,
    const float* __restrict__ musW, const float* __restrict__ musb,
    const float* __restrict__ varsW, const float* __restrict__ varsb,
    const float* __restrict__ mucW, const float* __restrict__ mucb,
    const float* __restrict__ varcW, const float* __restrict__ varcb,
    const float* __restrict__ eps_s, const float* __restrict__ eps_c,
    float* __restrict__ out, float* __restrict__ zin)
{
    int gw   = (blockIdx.x << 3) + (threadIdx.x >> 5);
    int lane = threadIdx.x & 31;
    int b = gw >> 8, idx = gw & 255;
    const __half* hh = hhi + b*H_;
    const __half* hl = hlo + b*H_;
    const float *Wm, *Wv; float bm, bv, ee;
    if (idx < 64) {
        Wm = musW + (long)idx*H_; Wv = varsW + (long)idx*H_;
        bm = musb[idx]; bv = varsb[idx]; ee = eps_s[b*64 + idx];
    } else {
        int cc = idx - 64;
        Wm = mucW + (long)cc*H_; Wv = varcW + (long)cc*H_;
        bm = mucb[cc]; bv = varcb[cc]; ee = eps_c[b*192 + cc];
    }
    float sm = 0.f, sv = 0.f;
    for (int k = lane; k < H_; k += 32) {
        float hv = __half2float(hh[k]) + __half2float(hl[k]);
        sm += hv*Wm[k]; sv += hv*Wv[k];
    }
    #pragma unroll
    for (int o = 16; o; o >>= 1) {
        sm += __shfl_xor_sync(0xffffffffu, sm, o);
        sv += __shfl_xor_sync(0xffffffffu, sv, o);
    }
    if (lane == 0) {
        float mu = sm + bm, lv = sv + bv;
        float samp = mu + ee * expf(0.5f*lv);
        zin[b*256 + idx] = samp;
        if (idx < 64) {
            out[OFF_MU_S  + b*64 + idx] = mu;
            out[OFF_LV_S  + b*64 + idx] = lv;
            out[OFF_STYLE + b*64 + idx] = samp;
        } else {
            int cc = idx - 64;
            out[OFF_MU_C    + b*192 + cc] = mu;
            out[OFF_LV_C    + b*192 + cc] = lv;
            out[OFF_CONTENT + b*192 + cc] = samp;
        }
    }
}

// ============================================================
// fc -> decoder initial state (writes fp16 hi/lo)
// ============================================================
__global__ void fc_kernel(const float* __restrict__ fcW, const float* __restrict__ fcb,
                          const float* __restrict__ zin,
                          __half* __restrict__ h0hi, __half* __restrict__ h0lo)
{
    int gw   = (blockIdx.x << 3) + (threadIdx.x >> 5);
    int lane = threadIdx.x & 31;
    int o = gw & 1023, b = gw >> 10;
    const float* zi = zin + b*256;
    const float* w  = fcW + (long)o*256;
    float s = 0.f;
    for (int k = lane; k < 256; k += 32) s += zi[k]*w[k];
    #pragma unroll
    for (int off = 16; off; off >>= 1) s += __shfl_xor_sync(0xffffffffu, s, off);
    if (lane == 0) {
        float v = s + fcb[o];
        __half hh = __float2half_rn(v);
        h0hi[b*H_ + o] = hh;
        h0lo[b*H_ + o] = __float2half_rn(v - __half2float(hh));
    }
}

// ============================================================
// fp32 -> fp16 convert for out_W
// ============================================================
__global__ void conv16_kernel(const float* __restrict__ src,
                              __half* __restrict__ dst, int n4)
{
    int i = blockIdx.x*blockDim.x + threadIdx.x;
    if (i >= n4) return;
    float4 v = ((const float4*)src)[i];
    __half2 p0, p1;
    p0.x = __float2half_rn(v.x); p0.y = __float2half_rn(v.y);
    p1.x = __float2half_rn(v.z); p1.y = __float2half_rn(v.w);
    ((__half2*)dst)[2*i]   = p0;
    ((__half2*)dst)[2*i+1] = p1;
}

// ============================================================
// Tensor-core logits GEMM (mma.sync fp16, SINGLE product):
// R13-proven body (4-stage cp.async pipeline, issue-ahead 3,
// 80B-pitch SMEM rows) — ONLY change vs R16: occupancy 2
// (launch_bounds(256,2); 2 x 80KB SMEM fits 228KB/SM).
// ============================================================
#define LG_STAGE_BYTES 20480           // 2 arrays * 128 rows * 80B
#define LG_SMEM_BYTES  (4*LG_STAGE_BYTES)

__device__ __forceinline__ void logits_issue_stage(
    unsigned sbase, int s, int kt, int tid, int bm, int bn,
    const __half* Ah, const __half* Bh)
{
    int k0 = kt << 5;
    const __half* bases[2] = {Ah, Bh};
    #pragma unroll
    for (int arr = 0; arr < 2; ++arr) {
        int rb = (arr < 1) ? bm : bn;
        #pragma unroll
        for (int c = 0; c < 2; ++c) {
            int ch = (tid << 1) + c;
            int row = ch >> 2, kc = ch & 3;
            unsigned dst = sbase + (unsigned)(s*LG_STAGE_BYTES + arr*10240 + row*80 + kc*16);
            const void* src = bases[arr] + (size_t)(rb + row)*H_ + k0 + (kc << 3);
            cpa16(dst, src);
        }
    }
}

__global__ void __launch_bounds__(256, 2) mma_logits(
    const __half* __restrict__ Ah, const __half* __restrict__ Bh,
    const float* __restrict__ bias, float* __restrict__ C)
{
    extern __shared__ char smem_raw[];
    unsigned sbase = (unsigned)__cvta_generic_to_shared(smem_raw);
    const int tid  = threadIdx.x;
    const int lane = tid & 31, warp = tid >> 5;
    const int wm = warp >> 2, wn = warp & 3;     // warp tile 64(m) x 32(n)
    const int bm = blockIdx.x << 7;              // 16 m-tiles (fast axis: share B in L2)
    const int bn = blockIdx.y << 7;              // 250 n-tiles

    float acc[4][4][4];
    #pragma unroll
    for (int mf = 0; mf < 4; ++mf)
        #pragma unroll
        for (int nf = 0; nf < 4; ++nf)
            #pragma unroll
            for (int q = 0; q < 4; ++q) acc[mf][nf][q] = 0.f;

    logits_issue_stage(sbase, 0, 0, tid, bm, bn, Ah, Bh); cp_commit();
    logits_issue_stage(sbase, 1, 1, tid, bm, bn, Ah, Bh); cp_commit();
    logits_issue_stage(sbase, 2, 2, tid, bm, bn, Ah, Bh); cp_commit();

    int stage = 0;         // = kt % 4
    #pragma unroll 1
    for (int kt = 0; kt < 32; ++kt) {
        if (kt < 30)       asm volatile("cp.async.wait_group 2;\n");
        else if (kt == 30) asm volatile("cp.async.wait_group 1;\n");
        else               asm volatile("cp.async.wait_group 0;\n");
        __syncthreads();

        unsigned sb = sbase + (unsigned)(stage*LG_STAGE_BYTES);
        #pragma unroll
        for (int kk = 0; kk < 2; ++kk) {
            uint32_t afh[4][4], bfh[4][2];
            #pragma unroll
            for (int mf = 0; mf < 4; ++mf) {
                int r = (wm << 6) + (mf << 4) + (lane & 15);
                unsigned off = sb + (unsigned)(r*80 + (kk << 5) + ((lane >> 4) << 4));
                ldsm_x4(afh[mf], off);
            }
            #pragma unroll
            for (int nf = 0; nf < 4; ++nf) {
                int r = (wn << 5) + (nf << 3) + (lane & 7);
                unsigned off = sb + 10240u + (unsigned)(r*80 + (kk << 5) + (((lane >> 3) & 1) << 4));
                ldsm_x2(bfh[nf], off);
            }
            #pragma unroll
            for (int mf = 0; mf < 4; ++mf)
                #pragma unroll
                for (int nf = 0; nf < 4; ++nf)
                    mma16816h(acc[mf][nf], afh[mf], bfh[nf]);
        }

        if (kt + 3 < 32) {
            int ws = stage + 3; if (ws >= 4) ws -= 4;
            logits_issue_stage(sbase, ws, kt + 3, tid, bm, bn, Ah, Bh);
            cp_commit();
        }
        stage = (stage + 1 >= 4) ? 0 : stage + 1;
    }

    // epilogue: add bias, write fp32
    #pragma unroll
    for (int mf = 0; mf < 4; ++mf) {
        #pragma unroll
        for (int nf = 0; nf < 4; ++nf) {
            int m0 = bm + (wm << 6) + (mf << 4) + (lane >> 2);
            int n0 = bn + (wn << 5) + (nf << 3) + ((lane & 3) << 1);
            float b0 = bias[n0], b1 = bias[n0 + 1];
            float2 v0, v1;
            v0.x = acc[mf][nf][0] + b0; v0.y = acc[mf][nf][1] + b1;
            v1.x = acc[mf][nf][2] + b0; v1.y = acc[mf][nf][3] + b1;
            *(float2*)&C[(size_t)m0*V_ + n0]       = v0;
            *(float2*)&C[(size_t)(m0+8)*V_ + n0]   = v1;
        }
    }
}

// ============================================================
// launch
// ============================================================
extern "C" void kernel_launch(void* const* d_in, const int* in_sizes, int n_in,
                              void* d_out, int out_size)
{
    const int*   x        = (const int*)  d_in[0];
    const int*   sos_tok  = (const int*)  d_in[1];
    const float* eps_s    = (const float*)d_in[2];
    const float* eps_c    = (const float*)d_in[3];
    const float* emb      = (const float*)d_in[4];
    const float* ln_g     = (const float*)d_in[5];
    const float* ln_b     = (const float*)d_in[6];
    const float* enc_Wih  = (const float*)d_in[7];
    const float* enc_Whh  = (const float*)d_in[8];
    const float* enc_bih  = (const float*)d_in[9];
    const float* enc_bhh  = (const float*)d_in[10];
    const float* mus_W    = (const float*)d_in[11];
    const float* mus_b    = (const float*)d_in[12];
    const float* vars_W   = (const float*)d_in[13];
    const float* vars_b   = (const float*)d_in[14];
    const float* muc_W    = (const float*)d_in[15];
    const float* muc_b    = (const float*)d_in[16];
    const float* varc_W   = (const float*)d_in[17];
    const float* varc_b   = (const float*)d_in[18];
    const float* fc_W     = (const float*)d_in[19];
    const float* fc_b     = (const float*)d_in[20];
    const float* dec_Wih  = (const float*)d_in[21];
    const float* dec_Whh  = (const float*)d_in[22];
    const float* dec_bih  = (const float*)d_in[23];
    const float* dec_bhh  = (const float*)d_in[24];
    const float* out_W    = (const float*)d_in[25];
    const float* out_b    = (const float*)d_in[26];
    float* out = (float*)d_out;

    float *pxge, *pxgd, *pzin;
    __half *peh, *pel, *pdinh, *pdinl, *pweh, *pwel, *pwdh, *pwdl;
    __half *pAhi, *pAlo, *pBhi, *pBlo, *pysh, *pW16;
    cudaGetSymbolAddress((void**)&pxge,  g_xg_enc);
    cudaGetSymbolAddress((void**)&pxgd,  g_xg_dec);
    cudaGetSymbolAddress((void**)&pzin,  g_zin);
    cudaGetSymbolAddress((void**)&peh,   g_eh);
    cudaGetSymbolAddress((void**)&pel,   g_el);
    cudaGetSymbolAddress((void**)&pdinh, g_dinh);
    cudaGetSymbolAddress((void**)&pdinl, g_dinl);
    cudaGetSymbolAddress((void**)&pweh,  g_wih_eh);
    cudaGetSymbolAddress((void**)&pwel,  g_wih_el);
    cudaGetSymbolAddress((void**)&pwdh,  g_wih_dh);
    cudaGetSymbolAddress((void**)&pwdl,  g_wih_dl);
    cudaGetSymbolAddress((void**)&pAhi,  g_hAhi);
    cudaGetSymbolAddress((void**)&pAlo,  g_hAlo);
    cudaGetSymbolAddress((void**)&pBhi,  g_hBhi);
    cudaGetSymbolAddress((void**)&pBlo,  g_hBlo);
    cudaGetSymbolAddress((void**)&pysh,  g_ys16h);
    cudaGetSymbolAddress((void**)&pW16,  g_W16);

    cudaFuncSetAttribute(gru_persistent_tc, cudaFuncAttributeMaxDynamicSharedMemorySize, GRU_SMEM_BYTES);
    cudaFuncSetAttribute(mma_logits,        cudaFuncAttributeMaxDynamicSharedMemorySize, LG_SMEM_BYTES);
    cudaFuncSetAttribute(mma_xg,            cudaFuncAttributeMaxDynamicSharedMemorySize, XG_SMEM_BYTES);

    // 1) fused embed + layernorm + fp16 hi/lo split + pad + din shift
    embed_ln_kernel<<<BT_ + 1, 128>>>(x, sos_tok, emb, ln_g, ln_b,
                                      peh, pel, pdinh, pdinl);

    // 2) out_W fp16 conversion + both weight split/pads (one launch)
    conv16_kernel<<<(V_*H_/4 + 255)/256, 256>>>(out_W, pW16, V_*H_/4);
    split_pad2_kernel<<<dim3((3*H_*EP_ + 255)/256, 1, 2), 256>>>(
        enc_Wih, pweh, pwel, dec_Wih, pwdh, pwdl, 3*H_);

    // 3) both input-gate GEMMs on tensor cores (3-product, ~1e-6 exact)
    mma_xg<<<dim3(BT_/128, XG_N/128, 2), 256, XG_SMEM_BYTES>>>(
        peh, pel, pweh, pwel, enc_bih, pxge,
        pdinh, pdinl, pwdh, pwdl, dec_bih, pxgd);

    // 4) encoder GRU (persistent, tensor-core); h0 = 0 in A pair
    init_enc_kernel<<<64, 256>>>(pAhi, pAlo);
    gru_persistent_tc<<<128, 256, GRU_SMEM_BYTES>>>(pxge, enc_Whh, enc_bhh,
                                                    pAhi, pAlo, pBhi, pBlo, nullptr);
    // final hn lands back in A pair (even step count)

    // 5) VAE heads + reparameterization
    heads_kernel<<<512, 256>>>(pAhi, pAlo, mus_W, mus_b, vars_W, vars_b,
                               muc_W, muc_b, varc_W, varc_b,
                               eps_s, eps_c, out, pzin);

    // 6) fc -> decoder initial state (B pair)
    fc_kernel<<<2048, 256>>>(fc_W, fc_b, pzin, pBhi, pBlo);

    // 7) decoder GRU (persistent, tensor-core), writes ys fp16 directly
    reset_bar_kernel<<<1, 1>>>();
    gru_persistent_tc<<<128, 256, GRU_SMEM_BYTES>>>(pxgd, dec_Whh, dec_bhh,
                                                    pBhi, pBlo, pAhi, pAlo, pysh);

    // 8) logits = ys @ out_W^T + out_b  via fp16 mma (single product)
    mma_logits<<<dim3(BT_/128, V_/128), 256, LG_SMEM_BYTES>>>(pysh, pW16, out_b, out);
}